// round 2
// baseline (speedup 1.0000x reference)
#include <cuda_runtime.h>
#include <math.h>

#define NBLK 32
#define CAP 1024
#define DK 256
#define DH 768
#define NQ 8192
#define CK 32

typedef unsigned long long ull;

// packed dual-fp32 FMA: d = a*b + d (element-wise on (lo,hi) pairs)
__device__ __forceinline__ void fma2(ull& d, ull a, ull b) {
    asm("fma.rn.f32x2 %0, %1, %2, %0;" : "+l"(d) : "l"(a), "l"(b));
}

// scratch (device globals: no allocation allowed)
__device__ float g_q[NQ * DK];   // layernormed queries, 8 MB
__device__ float g_r[NQ * DK];   // retrieved values, 8 MB

// ---------------------------------------------------------------------------
// Kernel A: q = LayerNorm(hs @ Wk + bk) * ln_w + ln_b      [8192,768]x[768,256]
// ---------------------------------------------------------------------------
__global__ __launch_bounds__(256) void qproj_ln_kernel(
    const float* __restrict__ hs, const float* __restrict__ Wk,
    const float* __restrict__ bk, const float* __restrict__ lnw,
    const float* __restrict__ lnb)
{
    __shared__ float As[64][16];
    __shared__ float Bs[16][256];
    const int tid = threadIdx.x;
    const int ty = tid >> 5;      // warp id 0..7  -> rows ty*8..ty*8+7
    const int tx = tid & 31;      // lane -> cols tx*8..tx*8+7
    const int m0 = blockIdx.x * 64;

    float c[8][8];
#pragma unroll
    for (int i = 0; i < 8; i++)
#pragma unroll
        for (int j = 0; j < 8; j++) c[i][j] = 0.f;

    for (int k0 = 0; k0 < DH; k0 += 16) {
        {
            int r = tid >> 2, k4 = tid & 3;
            float4 v = *(const float4*)(hs + (size_t)(m0 + r) * DH + k0 + k4 * 4);
            *(float4*)(&As[r][k4 * 4]) = v;
        }
#pragma unroll
        for (int u = 0; u < 4; u++) {
            int idx4 = tid + u * 256;
            int kk = idx4 >> 6, c4 = idx4 & 63;
            float4 v = *(const float4*)(Wk + (size_t)(k0 + kk) * DK + c4 * 4);
            *(float4*)(&Bs[kk][c4 * 4]) = v;
        }
        __syncthreads();
#pragma unroll
        for (int kk = 0; kk < 16; kk++) {
            float a[8], b[8];
#pragma unroll
            for (int i = 0; i < 8; i++) a[i] = As[ty * 8 + i][kk];
            float4 b0 = *(float4*)(&Bs[kk][tx * 8]);
            float4 b1 = *(float4*)(&Bs[kk][tx * 8 + 4]);
            b[0] = b0.x; b[1] = b0.y; b[2] = b0.z; b[3] = b0.w;
            b[4] = b1.x; b[5] = b1.y; b[6] = b1.z; b[7] = b1.w;
#pragma unroll
            for (int i = 0; i < 8; i++)
#pragma unroll
                for (int j = 0; j < 8; j++) c[i][j] += a[i] * b[j];
        }
        __syncthreads();
    }

    float bkv[8], lw[8], lb[8];
#pragma unroll
    for (int j = 0; j < 8; j++) {
        int col = tx * 8 + j;
        bkv[j] = bk[col]; lw[j] = lnw[col]; lb[j] = lnb[col];
    }
#pragma unroll
    for (int i = 0; i < 8; i++)
#pragma unroll
        for (int j = 0; j < 8; j++) c[i][j] += bkv[j];

#pragma unroll
    for (int i = 0; i < 8; i++) {
        float s = 0.f;
#pragma unroll
        for (int j = 0; j < 8; j++) s += c[i][j];
#pragma unroll
        for (int o = 16; o > 0; o >>= 1) s += __shfl_xor_sync(0xffffffffu, s, o);
        float mu = s * (1.0f / 256.0f);
        float v = 0.f;
#pragma unroll
        for (int j = 0; j < 8; j++) { float d = c[i][j] - mu; v += d * d; }
#pragma unroll
        for (int o = 16; o > 0; o >>= 1) v += __shfl_xor_sync(0xffffffffu, v, o);
        float rs = rsqrtf(v * (1.0f / 256.0f) + 1e-5f);
        float out[8];
#pragma unroll
        for (int j = 0; j < 8; j++) out[j] = (c[i][j] - mu) * rs * lw[j] + lb[j];
        float* dst = g_q + (size_t)(m0 + ty * 8 + i) * DK + tx * 8;
        *(float4*)dst       = make_float4(out[0], out[1], out[2], out[3]);
        *(float4*)(dst + 4) = make_float4(out[4], out[5], out[6], out[7]);
    }
}

// ---------------------------------------------------------------------------
// Kernel B: per-block masked softmax attention, summed over blocks.
// CTA = 64 queries x all 32 memory blocks, streamed in 32-key chunks.
// f32x2 packed FMA throughout the two GEMM loops (2x fp32 rate on sm_103a).
// Smem layouts feed f32x2 directly:
//   Kt2[key][130] float2 : key-major d-pairs -> 1 LDS.128 = 2 pairs per lane
//   Ps2[key][row] float2 : p duplicated (p,p) -> broadcast LDS.64, no packing
// Chunks beyond block_usage[b] are skipped (expected ~48% of dense work).
// ---------------------------------------------------------------------------
#define KT2_STRIDE 130   // float2 units; pad so 8-lane LDS.128 phases are conflict-free
#define PS2_STRIDE 65    // float2 units

extern __shared__ float smem_attn[];

__global__ __launch_bounds__(512, 1) void attn_kernel(
    const float* __restrict__ mk, const float* __restrict__ mv,
    const int* __restrict__ usage)
{
    float*  Qs  = smem_attn;                        // [64][256]       65536 B
    float*  Vs  = Qs + 64 * 256;                    // [32][256]       32768 B
    float2* Kt2 = (float2*)(Vs + 32 * 256);         // [32][130]       33280 B
    float2* Ps2 = Kt2 + 32 * KT2_STRIDE;            // [32][65] (p,p)  16640 B

    const int tid = threadIdx.x;
    const int ty = tid >> 5;          // warp 0..15 -> query rows ty*4..+3
    const int tx = tid & 31;          // lane = key id (QK^T) / col pairs (P@V)
    const int q0 = blockIdx.x * 64;

    // load Q tile (reused against all 32768 keys)
#pragma unroll
    for (int u = 0; u < 8; u++) {
        int idx4 = tid + u * 512;
        int r = idx4 >> 6, c4 = idx4 & 63;
        float4 v = *(const float4*)(g_q + (size_t)(q0 + r) * DK + c4 * 4);
        *(float4*)(Qs + r * 256 + c4 * 4) = v;
    }

    float O[4][8];
#pragma unroll
    for (int i = 0; i < 4; i++)
#pragma unroll
        for (int j = 0; j < 8; j++) O[i][j] = 0.f;

    const ulonglong2* krow = (const ulonglong2*)(Kt2 + tx * KT2_STRIDE);

    for (int b = 0; b < NBLK; b++) {
        const int use = __ldg(usage + b);
        const int nch = (use + CK - 1) / CK;

        ull acc2[4][4];
#pragma unroll
        for (int i = 0; i < 4; i++)
#pragma unroll
            for (int j = 0; j < 4; j++) acc2[i][j] = 0ull;
        float l[4] = {0.f, 0.f, 0.f, 0.f};

        for (int ch = 0; ch < nch; ch++) {
            const int c0 = ch * CK;
            __syncthreads();   // previous chunk's Ps2/Vs/Kt2 consumed
            // load K chunk (pair layout) + V chunk; STS.128, conflict-free
            const float* kb = mk + ((size_t)b * CAP + c0) * DK;
            const float* vb = mv + ((size_t)b * CAP + c0) * DK;
#pragma unroll
            for (int u = 0; u < 4; u++) {
                int idx4 = tid + u * 512;
                int key = idx4 >> 6, d4 = idx4 & 63;
                float4 kv = *(const float4*)(kb + (size_t)key * DK + d4 * 4);
                *(float4*)(Kt2 + key * KT2_STRIDE + d4 * 2) = kv;  // 2 pairs
                float4 vv = *(const float4*)(vb + (size_t)key * DK + d4 * 4);
                *(float4*)(Vs + key * 256 + d4 * 4) = vv;
            }
            __syncthreads();

            // S = Q K^T : lane tx owns key tx; packed pairs along d
            ull s2[4] = {0ull, 0ull, 0ull, 0ull};
#pragma unroll 8
            for (int d4 = 0; d4 < 64; d4++) {
                ulonglong2 k2 = krow[d4];   // 2 d-pairs of key tx
#pragma unroll
                for (int i = 0; i < 4; i++) {
                    ulonglong2 q2 = *(const ulonglong2*)(Qs + (ty * 4 + i) * 256 + d4 * 4);
                    fma2(s2[i], q2.x, k2.x);
                    fma2(s2[i], q2.y, k2.y);
                }
            }
            const bool valid = (c0 + tx) < use;
#pragma unroll
            for (int i = 0; i < 4; i++) {
                float2 sf = *(float2*)&s2[i];
                float s = sf.x + sf.y;
                float p = valid ? __expf(s * 0.0625f) : 0.f;
                l[i] += p;
                Ps2[tx * PS2_STRIDE + ty * 4 + i] = make_float2(p, p);
            }
            __syncthreads();

            // acc += P @ V : rows ty*4..+3, col pairs tx*4..+3 (8 floats)
#pragma unroll 4
            for (int c = 0; c < CK; c++) {
                ulonglong2 v0 = *(const ulonglong2*)(Vs + c * 256 + tx * 8);
                ulonglong2 v1 = *(const ulonglong2*)(Vs + c * 256 + tx * 8 + 4);
                const ull* pr = (const ull*)(Ps2 + c * PS2_STRIDE + ty * 4);
#pragma unroll
                for (int i = 0; i < 4; i++) {
                    ull pp = pr[i];   // broadcast (p,p)
                    fma2(acc2[i][0], pp, v0.x);
                    fma2(acc2[i][1], pp, v0.y);
                    fma2(acc2[i][2], pp, v1.x);
                    fma2(acc2[i][3], pp, v1.y);
                }
            }
        }
        // finalize block: O += acc / sum_exp   (lanes hold partial l per key)
#pragma unroll
        for (int i = 0; i < 4; i++) {
            float ls = l[i];
#pragma unroll
            for (int o = 16; o > 0; o >>= 1) ls += __shfl_xor_sync(0xffffffffu, ls, o);
            float rl = 1.0f / ls;
#pragma unroll
            for (int j = 0; j < 4; j++) {
                float2 a = *(float2*)&acc2[i][j];
                O[i][2 * j]     += a.x * rl;
                O[i][2 * j + 1] += a.y * rl;
            }
        }
    }

#pragma unroll
    for (int i = 0; i < 4; i++) {
        float* dst = g_r + (size_t)(q0 + ty * 4 + i) * DK + tx * 8;
        *(float4*)dst       = make_float4(O[i][0], O[i][1], O[i][2], O[i][3]);
        *(float4*)(dst + 4) = make_float4(O[i][4], O[i][5], O[i][6], O[i][7]);
    }
}

// ---------------------------------------------------------------------------
// Kernel C: out = retrieved @ Wo + bo          [8192,256]x[256,768]
// ---------------------------------------------------------------------------
__global__ __launch_bounds__(256) void out_gemm_kernel(
    const float* __restrict__ Wo, const float* __restrict__ bo,
    float* __restrict__ out)
{
    __shared__ float As[64][20];
    __shared__ float Bs[16][64];
    const int tid = threadIdx.x;
    const int ty = tid >> 4;      // 0..15 -> rows ty*4..+3
    const int tx = tid & 15;      // cols tx*4..+3
    const int m0 = blockIdx.x * 64;
    const int n0 = blockIdx.y * 64;

    float c[4][4];
#pragma unroll
    for (int i = 0; i < 4; i++)
#pragma unroll
        for (int j = 0; j < 4; j++) c[i][j] = 0.f;

    for (int k0 = 0; k0 < DK; k0 += 16) {
        {
            int r = tid >> 2, k4 = tid & 3;
            float4 v = *(const float4*)(g_r + (size_t)(m0 + r) * DK + k0 + k4 * 4);
            *(float4*)(&As[r][k4 * 4]) = v;
        }
        {
            int kk = tid >> 4, c4 = tid & 15;
            float4 v = *(const float4*)(Wo + (size_t)(k0 + kk) * DH + n0 + c4 * 4);
            *(float4*)(&Bs[kk][c4 * 4]) = v;
        }
        __syncthreads();
#pragma unroll
        for (int kk = 0; kk < 16; kk++) {
            float a[4];
#pragma unroll
            for (int i = 0; i < 4; i++) a[i] = As[ty * 4 + i][kk];
            float4 bv = *(float4*)(&Bs[kk][tx * 4]);
            float b[4] = {bv.x, bv.y, bv.z, bv.w};
#pragma unroll
            for (int i = 0; i < 4; i++)
#pragma unroll
                for (int j = 0; j < 4; j++) c[i][j] += a[i] * b[j];
        }
        __syncthreads();
    }

    float4 bv = *(const float4*)(bo + n0 + tx * 4);
    float bb[4] = {bv.x, bv.y, bv.z, bv.w};
#pragma unroll
    for (int i = 0; i < 4; i++) {
        float4 r = make_float4(c[i][0] + bb[0], c[i][1] + bb[1],
                               c[i][2] + bb[2], c[i][3] + bb[3]);
        *(float4*)(out + (size_t)(m0 + ty * 4 + i) * DH + n0 + tx * 4) = r;
    }
}

// ---------------------------------------------------------------------------
extern "C" void kernel_launch(void* const* d_in, const int* in_sizes, int n_in,
                              void* d_out, int out_size)
{
    const float* hs  = (const float*)d_in[0];
    const float* Wk  = (const float*)d_in[1];
    const float* bk  = (const float*)d_in[2];
    const float* lnw = (const float*)d_in[3];
    const float* lnb = (const float*)d_in[4];
    const float* mk  = (const float*)d_in[5];
    const float* mv  = (const float*)d_in[6];
    const float* Wo  = (const float*)d_in[7];
    const float* bo  = (const float*)d_in[8];
    const int* usage = (const int*)d_in[9];
    float* out = (float*)d_out;

    const int attn_smem = (64 * 256 + 32 * 256) * (int)sizeof(float)
                        + (32 * KT2_STRIDE + 32 * PS2_STRIDE) * (int)sizeof(float2);
    cudaFuncSetAttribute(attn_kernel, cudaFuncAttributeMaxDynamicSharedMemorySize, attn_smem);

    qproj_ln_kernel<<<NQ / 64, 256>>>(hs, Wk, bk, lnw, lnb);
    attn_kernel<<<NQ / 64, 512, attn_smem>>>(mk, mv, usage);
    dim3 gc(NQ / 64, DH / 64);
    out_gemm_kernel<<<gc, 256>>>(Wo, bo, out);
}

// round 3
// speedup vs baseline: 1.0021x; 1.0021x over previous
#include <cuda_runtime.h>
#include <math.h>

#define NBLK 32
#define CAP 1024
#define DK 256
#define DH 768
#define NQ 8192
#define CK 32

typedef unsigned long long ull;

// packed dual-fp32 FMA: d = a*b + d (element-wise on (lo,hi) pairs)
__device__ __forceinline__ void fma2(ull& d, ull a, ull b) {
    asm("fma.rn.f32x2 %0, %1, %2, %0;" : "+l"(d) : "l"(a), "l"(b));
}

// scratch (device globals: no allocation allowed)
__device__ float g_q[NQ * DK];   // layernormed queries, 8 MB
__device__ float g_r[NQ * DK];   // retrieved values, 8 MB

// ---------------------------------------------------------------------------
// Kernel A: q = LayerNorm(hs @ Wk + bk) * ln_w + ln_b      [8192,768]x[768,256]
// ---------------------------------------------------------------------------
__global__ __launch_bounds__(256) void qproj_ln_kernel(
    const float* __restrict__ hs, const float* __restrict__ Wk,
    const float* __restrict__ bk, const float* __restrict__ lnw,
    const float* __restrict__ lnb)
{
    __shared__ float As[64][16];
    __shared__ float Bs[16][256];
    const int tid = threadIdx.x;
    const int ty = tid >> 5;      // warp id 0..7  -> rows ty*8..ty*8+7
    const int tx = tid & 31;      // lane -> cols tx*8..tx*8+7
    const int m0 = blockIdx.x * 64;

    float c[8][8];
#pragma unroll
    for (int i = 0; i < 8; i++)
#pragma unroll
        for (int j = 0; j < 8; j++) c[i][j] = 0.f;

    for (int k0 = 0; k0 < DH; k0 += 16) {
        {
            int r = tid >> 2, k4 = tid & 3;
            float4 v = *(const float4*)(hs + (size_t)(m0 + r) * DH + k0 + k4 * 4);
            *(float4*)(&As[r][k4 * 4]) = v;
        }
#pragma unroll
        for (int u = 0; u < 4; u++) {
            int idx4 = tid + u * 256;
            int kk = idx4 >> 6, c4 = idx4 & 63;
            float4 v = *(const float4*)(Wk + (size_t)(k0 + kk) * DK + c4 * 4);
            *(float4*)(&Bs[kk][c4 * 4]) = v;
        }
        __syncthreads();
#pragma unroll
        for (int kk = 0; kk < 16; kk++) {
            float a[8], b[8];
#pragma unroll
            for (int i = 0; i < 8; i++) a[i] = As[ty * 8 + i][kk];
            float4 b0 = *(float4*)(&Bs[kk][tx * 8]);
            float4 b1 = *(float4*)(&Bs[kk][tx * 8 + 4]);
            b[0] = b0.x; b[1] = b0.y; b[2] = b0.z; b[3] = b0.w;
            b[4] = b1.x; b[5] = b1.y; b[6] = b1.z; b[7] = b1.w;
#pragma unroll
            for (int i = 0; i < 8; i++)
#pragma unroll
                for (int j = 0; j < 8; j++) c[i][j] += a[i] * b[j];
        }
        __syncthreads();
    }

    float bkv[8], lw[8], lb[8];
#pragma unroll
    for (int j = 0; j < 8; j++) {
        int col = tx * 8 + j;
        bkv[j] = bk[col]; lw[j] = lnw[col]; lb[j] = lnb[col];
    }
#pragma unroll
    for (int i = 0; i < 8; i++)
#pragma unroll
        for (int j = 0; j < 8; j++) c[i][j] += bkv[j];

#pragma unroll
    for (int i = 0; i < 8; i++) {
        float s = 0.f;
#pragma unroll
        for (int j = 0; j < 8; j++) s += c[i][j];
#pragma unroll
        for (int o = 16; o > 0; o >>= 1) s += __shfl_xor_sync(0xffffffffu, s, o);
        float mu = s * (1.0f / 256.0f);
        float v = 0.f;
#pragma unroll
        for (int j = 0; j < 8; j++) { float d = c[i][j] - mu; v += d * d; }
#pragma unroll
        for (int o = 16; o > 0; o >>= 1) v += __shfl_xor_sync(0xffffffffu, v, o);
        float rs = rsqrtf(v * (1.0f / 256.0f) + 1e-5f);
        float out[8];
#pragma unroll
        for (int j = 0; j < 8; j++) out[j] = (c[i][j] - mu) * rs * lw[j] + lb[j];
        float* dst = g_q + (size_t)(m0 + ty * 8 + i) * DK + tx * 8;
        *(float4*)dst       = make_float4(out[0], out[1], out[2], out[3]);
        *(float4*)(dst + 4) = make_float4(out[4], out[5], out[6], out[7]);
    }
}

// ---------------------------------------------------------------------------
// Kernel B: per-block masked softmax attention, summed over blocks.
// CTA = 64 queries x all 32 memory blocks, streamed in 32-key chunks.
// f32x2 packed FMA throughout the two GEMM loops (2x fp32 rate on sm_103a).
// Smem layouts feed f32x2 directly:
//   Kt2[key][130] float2 : key-major d-pairs -> 1 LDS.128 = 2 pairs per lane
//   Ps2[key][row] float2 : p duplicated (p,p) -> broadcast LDS.64, no packing
// Chunks beyond block_usage[b] are skipped (expected ~48% of dense work).
// ---------------------------------------------------------------------------
#define KT2_STRIDE 130   // float2 units; pad so 8-lane LDS.128 phases are conflict-free
#define PS2_STRIDE 65    // float2 units

extern __shared__ float smem_attn[];

__global__ __launch_bounds__(512, 1) void attn_kernel(
    const float* __restrict__ mk, const float* __restrict__ mv,
    const int* __restrict__ usage)
{
    float*  Qs  = smem_attn;                        // [64][256]       65536 B
    float*  Vs  = Qs + 64 * 256;                    // [32][256]       32768 B
    float2* Kt2 = (float2*)(Vs + 32 * 256);         // [32][130]       33280 B
    float2* Ps2 = Kt2 + 32 * KT2_STRIDE;            // [32][65] (p,p)  16640 B

    const int tid = threadIdx.x;
    const int ty = tid >> 5;          // warp 0..15 -> query rows ty*4..+3
    const int tx = tid & 31;          // lane = key id (QK^T) / col pairs (P@V)
    const int q0 = blockIdx.x * 64;

    // load Q tile (reused against all 32768 keys)
#pragma unroll
    for (int u = 0; u < 8; u++) {
        int idx4 = tid + u * 512;
        int r = idx4 >> 6, c4 = idx4 & 63;
        float4 v = *(const float4*)(g_q + (size_t)(q0 + r) * DK + c4 * 4);
        *(float4*)(Qs + r * 256 + c4 * 4) = v;
    }

    float O[4][8];
#pragma unroll
    for (int i = 0; i < 4; i++)
#pragma unroll
        for (int j = 0; j < 8; j++) O[i][j] = 0.f;

    const ulonglong2* krow = (const ulonglong2*)(Kt2 + tx * KT2_STRIDE);

    for (int b = 0; b < NBLK; b++) {
        const int use = __ldg(usage + b);
        const int nch = (use + CK - 1) / CK;

        ull acc2[4][4];
#pragma unroll
        for (int i = 0; i < 4; i++)
#pragma unroll
            for (int j = 0; j < 4; j++) acc2[i][j] = 0ull;
        float l[4] = {0.f, 0.f, 0.f, 0.f};

        for (int ch = 0; ch < nch; ch++) {
            const int c0 = ch * CK;
            __syncthreads();   // previous chunk's Ps2/Vs/Kt2 consumed
            // load K chunk (pair layout) + V chunk; STS.128, conflict-free
            const float* kb = mk + ((size_t)b * CAP + c0) * DK;
            const float* vb = mv + ((size_t)b * CAP + c0) * DK;
#pragma unroll
            for (int u = 0; u < 4; u++) {
                int idx4 = tid + u * 512;
                int key = idx4 >> 6, d4 = idx4 & 63;
                float4 kv = *(const float4*)(kb + (size_t)key * DK + d4 * 4);
                *(float4*)(Kt2 + key * KT2_STRIDE + d4 * 2) = kv;  // 2 pairs
                float4 vv = *(const float4*)(vb + (size_t)key * DK + d4 * 4);
                *(float4*)(Vs + key * 256 + d4 * 4) = vv;
            }
            __syncthreads();

            // S = Q K^T : lane tx owns key tx; packed pairs along d
            ull s2[4] = {0ull, 0ull, 0ull, 0ull};
#pragma unroll 8
            for (int d4 = 0; d4 < 64; d4++) {
                ulonglong2 k2 = krow[d4];   // 2 d-pairs of key tx
#pragma unroll
                for (int i = 0; i < 4; i++) {
                    ulonglong2 q2 = *(const ulonglong2*)(Qs + (ty * 4 + i) * 256 + d4 * 4);
                    fma2(s2[i], q2.x, k2.x);
                    fma2(s2[i], q2.y, k2.y);
                }
            }
            const bool valid = (c0 + tx) < use;
#pragma unroll
            for (int i = 0; i < 4; i++) {
                float2 sf = *(float2*)&s2[i];
                float s = sf.x + sf.y;
                float p = valid ? __expf(s * 0.0625f) : 0.f;
                l[i] += p;
                Ps2[tx * PS2_STRIDE + ty * 4 + i] = make_float2(p, p);
            }
            __syncthreads();

            // acc += P @ V : rows ty*4..+3, col pairs tx*4..+3 (8 floats)
#pragma unroll 4
            for (int c = 0; c < CK; c++) {
                ulonglong2 v0 = *(const ulonglong2*)(Vs + c * 256 + tx * 8);
                ulonglong2 v1 = *(const ulonglong2*)(Vs + c * 256 + tx * 8 + 4);
                const ull* pr = (const ull*)(Ps2 + c * PS2_STRIDE + ty * 4);
#pragma unroll
                for (int i = 0; i < 4; i++) {
                    ull pp = pr[i];   // broadcast (p,p)
                    fma2(acc2[i][0], pp, v0.x);
                    fma2(acc2[i][1], pp, v0.y);
                    fma2(acc2[i][2], pp, v1.x);
                    fma2(acc2[i][3], pp, v1.y);
                }
            }
        }
        // finalize block: O += acc / sum_exp   (lanes hold partial l per key)
#pragma unroll
        for (int i = 0; i < 4; i++) {
            float ls = l[i];
#pragma unroll
            for (int o = 16; o > 0; o >>= 1) ls += __shfl_xor_sync(0xffffffffu, ls, o);
            float rl = 1.0f / ls;
#pragma unroll
            for (int j = 0; j < 4; j++) {
                float2 a = *(float2*)&acc2[i][j];
                O[i][2 * j]     += a.x * rl;
                O[i][2 * j + 1] += a.y * rl;
            }
        }
    }

#pragma unroll
    for (int i = 0; i < 4; i++) {
        float* dst = g_r + (size_t)(q0 + ty * 4 + i) * DK + tx * 8;
        *(float4*)dst       = make_float4(O[i][0], O[i][1], O[i][2], O[i][3]);
        *(float4*)(dst + 4) = make_float4(O[i][4], O[i][5], O[i][6], O[i][7]);
    }
}

// ---------------------------------------------------------------------------
// Kernel C: out = retrieved @ Wo + bo          [8192,256]x[256,768]
// ---------------------------------------------------------------------------
__global__ __launch_bounds__(256) void out_gemm_kernel(
    const float* __restrict__ Wo, const float* __restrict__ bo,
    float* __restrict__ out)
{
    __shared__ float As[64][20];
    __shared__ float Bs[16][64];
    const int tid = threadIdx.x;
    const int ty = tid >> 4;      // 0..15 -> rows ty*4..+3
    const int tx = tid & 15;      // cols tx*4..+3
    const int m0 = blockIdx.x * 64;
    const int n0 = blockIdx.y * 64;

    float c[4][4];
#pragma unroll
    for (int i = 0; i < 4; i++)
#pragma unroll
        for (int j = 0; j < 4; j++) c[i][j] = 0.f;

    for (int k0 = 0; k0 < DK; k0 += 16) {
        {
            int r = tid >> 2, k4 = tid & 3;
            float4 v = *(const float4*)(g_r + (size_t)(m0 + r) * DK + k0 + k4 * 4);
            *(float4*)(&As[r][k4 * 4]) = v;
        }
        {
            int kk = tid >> 4, c4 = tid & 15;
            float4 v = *(const float4*)(Wo + (size_t)(k0 + kk) * DH + n0 + c4 * 4);
            *(float4*)(&Bs[kk][c4 * 4]) = v;
        }
        __syncthreads();
#pragma unroll
        for (int kk = 0; kk < 16; kk++) {
            float a[4];
#pragma unroll
            for (int i = 0; i < 4; i++) a[i] = As[ty * 4 + i][kk];
            float4 bv = *(float4*)(&Bs[kk][tx * 4]);
            float b[4] = {bv.x, bv.y, bv.z, bv.w};
#pragma unroll
            for (int i = 0; i < 4; i++)
#pragma unroll
                for (int j = 0; j < 4; j++) c[i][j] += a[i] * b[j];
        }
        __syncthreads();
    }

    float4 bv = *(const float4*)(bo + n0 + tx * 4);
    float bb[4] = {bv.x, bv.y, bv.z, bv.w};
#pragma unroll
    for (int i = 0; i < 4; i++) {
        float4 r = make_float4(c[i][0] + bb[0], c[i][1] + bb[1],
                               c[i][2] + bb[2], c[i][3] + bb[3]);
        *(float4*)(out + (size_t)(m0 + ty * 4 + i) * DH + n0 + tx * 4) = r;
    }
}

// ---------------------------------------------------------------------------
extern "C" void kernel_launch(void* const* d_in, const int* in_sizes, int n_in,
                              void* d_out, int out_size)
{
    const float* hs  = (const float*)d_in[0];
    const float* Wk  = (const float*)d_in[1];
    const float* bk  = (const float*)d_in[2];
    const float* lnw = (const float*)d_in[3];
    const float* lnb = (const float*)d_in[4];
    const float* mk  = (const float*)d_in[5];
    const float* mv  = (const float*)d_in[6];
    const float* Wo  = (const float*)d_in[7];
    const float* bo  = (const float*)d_in[8];
    const int* usage = (const int*)d_in[9];
    float* out = (float*)d_out;

    const int attn_smem = (64 * 256 + 32 * 256) * (int)sizeof(float)
                        + (32 * KT2_STRIDE + 32 * PS2_STRIDE) * (int)sizeof(float2);
    cudaFuncSetAttribute(attn_kernel, cudaFuncAttributeMaxDynamicSharedMemorySize, attn_smem);

    qproj_ln_kernel<<<NQ / 64, 256>>>(hs, Wk, bk, lnw, lnb);
    attn_kernel<<<NQ / 64, 512, attn_smem>>>(mk, mv, usage);
    dim3 gc(NQ / 64, DH / 64);
    out_gemm_kernel<<<gc, 256>>>(Wo, bo, out);
}

// round 4
// speedup vs baseline: 3.5008x; 3.4936x over previous
#include <cuda_runtime.h>
#include <math.h>

#define NBLK 32
#define CAP 1024
#define DK 256
#define DH 768
#define NQ 8192

// scratch (device globals: no allocation allowed)
__device__ float g_q[NQ * DK];   // layernormed queries
__device__ float g_r[NQ * DK];   // retrieved values

__device__ __forceinline__ unsigned tf32r(float x) {
    unsigned r; asm("cvt.rna.tf32.f32 %0, %1;" : "=r"(r) : "f"(x)); return r;
}

__device__ __forceinline__ void mma_tf32(
    float& d0, float& d1, float& d2, float& d3,
    unsigned a0, unsigned a1, unsigned a2, unsigned a3,
    unsigned b0, unsigned b1)
{
    asm("mma.sync.aligned.m16n8k8.row.col.f32.tf32.tf32.f32 "
        "{%0,%1,%2,%3}, {%4,%5,%6,%7}, {%8,%9}, {%0,%1,%2,%3};"
        : "+f"(d0), "+f"(d1), "+f"(d2), "+f"(d3)
        : "r"(a0), "r"(a1), "r"(a2), "r"(a3), "r"(b0), "r"(b1));
}

// ---------------------------------------------------------------------------
// Kernel A: q = LayerNorm(hs @ Wk + bk) * ln_w + ln_b      [8192,768]x[768,256]
// ---------------------------------------------------------------------------
__global__ __launch_bounds__(256) void qproj_ln_kernel(
    const float* __restrict__ hs, const float* __restrict__ Wk,
    const float* __restrict__ bk, const float* __restrict__ lnw,
    const float* __restrict__ lnb)
{
    __shared__ float As[64][16];
    __shared__ float Bs[16][256];
    const int tid = threadIdx.x;
    const int ty = tid >> 5;
    const int tx = tid & 31;
    const int m0 = blockIdx.x * 64;

    float c[8][8];
#pragma unroll
    for (int i = 0; i < 8; i++)
#pragma unroll
        for (int j = 0; j < 8; j++) c[i][j] = 0.f;

    for (int k0 = 0; k0 < DH; k0 += 16) {
        {
            int r = tid >> 2, k4 = tid & 3;
            float4 v = *(const float4*)(hs + (size_t)(m0 + r) * DH + k0 + k4 * 4);
            *(float4*)(&As[r][k4 * 4]) = v;
        }
#pragma unroll
        for (int u = 0; u < 4; u++) {
            int idx4 = tid + u * 256;
            int kk = idx4 >> 6, c4 = idx4 & 63;
            float4 v = *(const float4*)(Wk + (size_t)(k0 + kk) * DK + c4 * 4);
            *(float4*)(&Bs[kk][c4 * 4]) = v;
        }
        __syncthreads();
#pragma unroll
        for (int kk = 0; kk < 16; kk++) {
            float a[8], b[8];
#pragma unroll
            for (int i = 0; i < 8; i++) a[i] = As[ty * 8 + i][kk];
            float4 b0 = *(float4*)(&Bs[kk][tx * 8]);
            float4 b1 = *(float4*)(&Bs[kk][tx * 8 + 4]);
            b[0] = b0.x; b[1] = b0.y; b[2] = b0.z; b[3] = b0.w;
            b[4] = b1.x; b[5] = b1.y; b[6] = b1.z; b[7] = b1.w;
#pragma unroll
            for (int i = 0; i < 8; i++)
#pragma unroll
                for (int j = 0; j < 8; j++) c[i][j] += a[i] * b[j];
        }
        __syncthreads();
    }

    float bkv[8], lw[8], lb[8];
#pragma unroll
    for (int j = 0; j < 8; j++) {
        int col = tx * 8 + j;
        bkv[j] = bk[col]; lw[j] = lnw[col]; lb[j] = lnb[col];
    }
#pragma unroll
    for (int i = 0; i < 8; i++)
#pragma unroll
        for (int j = 0; j < 8; j++) c[i][j] += bkv[j];

#pragma unroll
    for (int i = 0; i < 8; i++) {
        float s = 0.f;
#pragma unroll
        for (int j = 0; j < 8; j++) s += c[i][j];
#pragma unroll
        for (int o = 16; o > 0; o >>= 1) s += __shfl_xor_sync(0xffffffffu, s, o);
        float mu = s * (1.0f / 256.0f);
        float v = 0.f;
#pragma unroll
        for (int j = 0; j < 8; j++) { float d = c[i][j] - mu; v += d * d; }
#pragma unroll
        for (int o = 16; o > 0; o >>= 1) v += __shfl_xor_sync(0xffffffffu, v, o);
        float rs = rsqrtf(v * (1.0f / 256.0f) + 1e-5f);
        float out[8];
#pragma unroll
        for (int j = 0; j < 8; j++) out[j] = (c[i][j] - mu) * rs * lw[j] + lb[j];
        float* dst = g_q + (size_t)(m0 + ty * 8 + i) * DK + tx * 8;
        *(float4*)dst       = make_float4(out[0], out[1], out[2], out[3]);
        *(float4*)(dst + 4) = make_float4(out[4], out[5], out[6], out[7]);
    }
}

// ---------------------------------------------------------------------------
// Kernel B: per-block masked softmax attention via tf32 tensor-core mma.
// CTA = 64 queries x all 32 memory blocks, chunks of 32 keys.
// 8 warps. QK^T: warp w -> m-tile (w>>1), n-tiles (w&1)*2+{0,1}.
//          P@V : warp w -> m-tile (w&3),  n-half  (w>>2) (128 cols, 16 n8-tiles).
// Strides: Q/K 260 (=4 mod 32), V 264 (=8 mod 32), P 36 -> all frag LDS
// bank-conflict-free. Row sums in Ls[64][2], unique writer per (row,half).
// exp without max-subtraction is exact vs reference; |s| << 1.
// ---------------------------------------------------------------------------
#define QS_STRIDE 260
#define KS_STRIDE 260
#define VS_STRIDE 264
#define PS_STRIDE 36

extern __shared__ unsigned smem_u[];

__global__ __launch_bounds__(256, 1) void attn_kernel(
    const float* __restrict__ mk, const float* __restrict__ mv,
    const int* __restrict__ usage)
{
    unsigned* Qs = smem_u;                       // [64][260]
    unsigned* Ks = Qs + 64 * QS_STRIDE;          // [32][260]
    unsigned* Vs = Ks + 32 * KS_STRIDE;          // [32][264]
    unsigned* Ps = Vs + 32 * VS_STRIDE;          // [64][36]
    float*    Ls = (float*)(Ps + 64 * PS_STRIDE);// [64][2]

    const int tid  = threadIdx.x;
    const int w    = tid >> 5;
    const int lane = tid & 31;
    const int gid  = lane >> 2;     // row group 0..7
    const int tq   = lane & 3;      // k/col group 0..3
    const int q0   = blockIdx.x * 64;

    const int mw  = w >> 1;         // QK m-tile
    const int nt0 = (w & 1) * 2;    // QK first n-tile
    const int mw2 = w & 3;          // PV m-tile
    const int nh  = w >> 2;         // PV n-half

    // load Q tile -> tf32 smem
#pragma unroll
    for (int u = 0; u < 16; u++) {
        int idx4 = tid + u * 256;
        int r = idx4 >> 6, c4 = idx4 & 63;
        float4 v = *(const float4*)(g_q + (size_t)(q0 + r) * DK + c4 * 4);
        *(uint4*)(Qs + r * QS_STRIDE + c4 * 4) =
            make_uint4(tf32r(v.x), tf32r(v.y), tf32r(v.z), tf32r(v.w));
    }

    float O[16][4];
#pragma unroll
    for (int t = 0; t < 16; t++)
#pragma unroll
        for (int j = 0; j < 4; j++) O[t][j] = 0.f;

    // per-lane frag base pointers
    const unsigned* qa  = Qs + (mw * 16 + gid) * QS_STRIDE + tq;
    const unsigned* kb0 = Ks + (nt0 * 8 + gid) * KS_STRIDE + tq;
    const unsigned* pa  = Ps + (mw2 * 16 + gid) * PS_STRIDE + tq;
    const unsigned* vb  = Vs + tq * VS_STRIDE + nh * 128 + gid;

    for (int b = 0; b < NBLK; b++) {
        const int use = __ldg(usage + b);
        const int nch = (use + 31) >> 5;

        float acc[16][4];
#pragma unroll
        for (int t = 0; t < 16; t++)
#pragma unroll
            for (int j = 0; j < 4; j++) acc[t][j] = 0.f;

        for (int ch = 0; ch < nch; ch++) {
            const int c0 = ch * 32;
            __syncthreads();   // previous chunk's Ks/Vs/Ps (+ Ls finalize reads) done
            const float* kg = mk + ((size_t)b * CAP + c0) * DK;
            const float* vg = mv + ((size_t)b * CAP + c0) * DK;
#pragma unroll
            for (int u = 0; u < 8; u++) {
                int idx4 = tid + u * 256;
                int key = idx4 >> 6, d4 = idx4 & 63;
                float4 kv = *(const float4*)(kg + (size_t)key * DK + d4 * 4);
                *(uint4*)(Ks + key * KS_STRIDE + d4 * 4) =
                    make_uint4(tf32r(kv.x), tf32r(kv.y), tf32r(kv.z), tf32r(kv.w));
                float4 vv = *(const float4*)(vg + (size_t)key * DK + d4 * 4);
                *(uint4*)(Vs + key * VS_STRIDE + d4 * 4) =
                    make_uint4(tf32r(vv.x), tf32r(vv.y), tf32r(vv.z), tf32r(vv.w));
            }
            if (ch == 0 && tid < 128) Ls[tid] = 0.f;
            __syncthreads();

            // ---- S = Q K^T (tf32 mma), warp's 2 n-tiles ----
            float s0[4] = {0.f, 0.f, 0.f, 0.f};
            float s1[4] = {0.f, 0.f, 0.f, 0.f};
#pragma unroll 8
            for (int kk = 0; kk < 32; kk++) {
                const int k0 = kk * 8;
                unsigned a0 = qa[k0];
                unsigned a1 = qa[k0 + 8 * QS_STRIDE];
                unsigned a2 = qa[k0 + 4];
                unsigned a3 = qa[k0 + 8 * QS_STRIDE + 4];
                unsigned b0 = kb0[k0], b1 = kb0[k0 + 4];
                mma_tf32(s0[0], s0[1], s0[2], s0[3], a0, a1, a2, a3, b0, b1);
                unsigned b2 = kb0[8 * KS_STRIDE + k0], b3 = kb0[8 * KS_STRIDE + k0 + 4];
                mma_tf32(s1[0], s1[1], s1[2], s1[3], a0, a1, a2, a3, b2, b3);
            }

            // ---- mask + exp + store P (tf32) + row-sum partials ----
            const int rem = use - c0;   // >= 1
            float rs0 = 0.f, rs8 = 0.f;
            {
                int colb = nt0 * 8 + tq * 2;
                bool v0 = colb < rem, v1 = colb + 1 < rem;
                float p0 = v0 ? __expf(s0[0] * 0.0625f) : 0.f;
                float p1 = v1 ? __expf(s0[1] * 0.0625f) : 0.f;
                float p2 = v0 ? __expf(s0[2] * 0.0625f) : 0.f;
                float p3 = v1 ? __expf(s0[3] * 0.0625f) : 0.f;
                rs0 += p0 + p1; rs8 += p2 + p3;
                unsigned* pr = Ps + (mw * 16 + gid) * PS_STRIDE + colb;
                pr[0] = tf32r(p0); pr[1] = tf32r(p1);
                pr[8 * PS_STRIDE] = tf32r(p2); pr[8 * PS_STRIDE + 1] = tf32r(p3);
            }
            {
                int colb = (nt0 + 1) * 8 + tq * 2;
                bool v0 = colb < rem, v1 = colb + 1 < rem;
                float p0 = v0 ? __expf(s1[0] * 0.0625f) : 0.f;
                float p1 = v1 ? __expf(s1[1] * 0.0625f) : 0.f;
                float p2 = v0 ? __expf(s1[2] * 0.0625f) : 0.f;
                float p3 = v1 ? __expf(s1[3] * 0.0625f) : 0.f;
                rs0 += p0 + p1; rs8 += p2 + p3;
                unsigned* pr = Ps + (mw * 16 + gid) * PS_STRIDE + colb;
                pr[0] = tf32r(p0); pr[1] = tf32r(p1);
                pr[8 * PS_STRIDE] = tf32r(p2); pr[8 * PS_STRIDE + 1] = tf32r(p3);
            }
            rs0 += __shfl_xor_sync(0xffffffffu, rs0, 1);
            rs0 += __shfl_xor_sync(0xffffffffu, rs0, 2);
            rs8 += __shfl_xor_sync(0xffffffffu, rs8, 1);
            rs8 += __shfl_xor_sync(0xffffffffu, rs8, 2);
            if (tq == 0) {   // unique writer per (row, half)
                Ls[(mw * 16 + gid) * 2 + (w & 1)]     += rs0;
                Ls[(mw * 16 + gid + 8) * 2 + (w & 1)] += rs8;
            }
            __syncthreads();   // P + Ls visible

            // ---- acc += P @ V ----
#pragma unroll
            for (int kk = 0; kk < 4; kk++) {
                unsigned a0 = pa[kk * 8];
                unsigned a1 = pa[kk * 8 + 8 * PS_STRIDE];
                unsigned a2 = pa[kk * 8 + 4];
                unsigned a3 = pa[kk * 8 + 8 * PS_STRIDE + 4];
                const unsigned* vk = vb + kk * 8 * VS_STRIDE;
#pragma unroll
                for (int nt = 0; nt < 16; nt++) {
                    unsigned b0 = vk[nt * 8];
                    unsigned b1 = vk[4 * VS_STRIDE + nt * 8];
                    mma_tf32(acc[nt][0], acc[nt][1], acc[nt][2], acc[nt][3],
                             a0, a1, a2, a3, b0, b1);
                }
            }
        }

        // ---- finalize block: O += acc / rowsum (Ls synced pre-PV) ----
        const int r0 = mw2 * 16 + gid;
        float rl0 = 1.0f / (Ls[r0 * 2] + Ls[r0 * 2 + 1]);
        float rl8 = 1.0f / (Ls[(r0 + 8) * 2] + Ls[(r0 + 8) * 2 + 1]);
#pragma unroll
        for (int nt = 0; nt < 16; nt++) {
            O[nt][0] += acc[nt][0] * rl0;
            O[nt][1] += acc[nt][1] * rl0;
            O[nt][2] += acc[nt][2] * rl8;
            O[nt][3] += acc[nt][3] * rl8;
        }
    }

    // write retrieved values
    const int row0 = q0 + mw2 * 16 + gid;
#pragma unroll
    for (int nt = 0; nt < 16; nt++) {
        int col = nh * 128 + nt * 8 + tq * 2;
        *(float2*)(g_r + (size_t)row0 * DK + col)       = make_float2(O[nt][0], O[nt][1]);
        *(float2*)(g_r + (size_t)(row0 + 8) * DK + col) = make_float2(O[nt][2], O[nt][3]);
    }
}

// ---------------------------------------------------------------------------
// Kernel C: out = retrieved @ Wo + bo          [8192,256]x[256,768]
// ---------------------------------------------------------------------------
__global__ __launch_bounds__(256) void out_gemm_kernel(
    const float* __restrict__ Wo, const float* __restrict__ bo,
    float* __restrict__ out)
{
    __shared__ float As[64][20];
    __shared__ float Bs[16][64];
    const int tid = threadIdx.x;
    const int ty = tid >> 4;
    const int tx = tid & 15;
    const int m0 = blockIdx.x * 64;
    const int n0 = blockIdx.y * 64;

    float c[4][4];
#pragma unroll
    for (int i = 0; i < 4; i++)
#pragma unroll
        for (int j = 0; j < 4; j++) c[i][j] = 0.f;

    for (int k0 = 0; k0 < DK; k0 += 16) {
        {
            int r = tid >> 2, k4 = tid & 3;
            float4 v = *(const float4*)(g_r + (size_t)(m0 + r) * DK + k0 + k4 * 4);
            *(float4*)(&As[r][k4 * 4]) = v;
        }
        {
            int kk = tid >> 4, c4 = tid & 15;
            float4 v = *(const float4*)(Wo + (size_t)(k0 + kk) * DH + n0 + c4 * 4);
            *(float4*)(&Bs[kk][c4 * 4]) = v;
        }
        __syncthreads();
#pragma unroll
        for (int kk = 0; kk < 16; kk++) {
            float a[4];
#pragma unroll
            for (int i = 0; i < 4; i++) a[i] = As[ty * 4 + i][kk];
            float4 bv = *(float4*)(&Bs[kk][tx * 4]);
            float b[4] = {bv.x, bv.y, bv.z, bv.w};
#pragma unroll
            for (int i = 0; i < 4; i++)
#pragma unroll
                for (int j = 0; j < 4; j++) c[i][j] += a[i] * b[j];
        }
        __syncthreads();
    }

    float4 bv = *(const float4*)(bo + n0 + tx * 4);
    float bb[4] = {bv.x, bv.y, bv.z, bv.w};
#pragma unroll
    for (int i = 0; i < 4; i++) {
        float4 r = make_float4(c[i][0] + bb[0], c[i][1] + bb[1],
                               c[i][2] + bb[2], c[i][3] + bb[3]);
        *(float4*)(out + (size_t)(m0 + ty * 4 + i) * DH + n0 + tx * 4) = r;
    }
}

// ---------------------------------------------------------------------------
extern "C" void kernel_launch(void* const* d_in, const int* in_sizes, int n_in,
                              void* d_out, int out_size)
{
    const float* hs  = (const float*)d_in[0];
    const float* Wk  = (const float*)d_in[1];
    const float* bk  = (const float*)d_in[2];
    const float* lnw = (const float*)d_in[3];
    const float* lnb = (const float*)d_in[4];
    const float* mk  = (const float*)d_in[5];
    const float* mv  = (const float*)d_in[6];
    const float* Wo  = (const float*)d_in[7];
    const float* bo  = (const float*)d_in[8];
    const int* usage = (const int*)d_in[9];
    float* out = (float*)d_out;

    const int attn_smem = (64 * QS_STRIDE + 32 * KS_STRIDE + 32 * VS_STRIDE
                         + 64 * PS_STRIDE + 128) * (int)sizeof(unsigned);
    cudaFuncSetAttribute(attn_kernel, cudaFuncAttributeMaxDynamicSharedMemorySize, attn_smem);

    qproj_ln_kernel<<<NQ / 64, 256>>>(hs, Wk, bk, lnw, lnb);
    attn_kernel<<<NQ / 64, 256, attn_smem>>>(mk, mv, usage);
    dim3 gc(NQ / 64, DH / 64);
    out_gemm_kernel<<<gc, 256>>>(Wo, bo, out);
}

// round 6
// speedup vs baseline: 5.1177x; 1.4619x over previous
#include <cuda_runtime.h>
#include <cuda_fp16.h>
#include <math.h>
#include <cstdint>

#define NBLK 32
#define CAP 1024
#define DK 256
#define DH 768
#define NQ 8192

typedef uint32_t u32;

// scratch (device globals: no allocation allowed)
__device__ __half g_qh[NQ * DK];            // layernormed queries, fp16
__device__ __half g_kh[NBLK * CAP * DK];    // keys, fp16
__device__ __half g_vth[NBLK * DK * CAP];   // values transposed [b][d][key], fp16
__device__ float  g_r0[NQ * DK];            // retrieved partial (blocks 0-15)
__device__ float  g_r1[NQ * DK];            // retrieved partial (blocks 16-31)

__device__ __forceinline__ u32 packh2(float a, float b) {
    __half2 h = __floats2half2_rn(a, b);
    return *(u32*)&h;
}

// fp16 tensor-core mma, fp32 accumulate
__device__ __forceinline__ void mma_f16(float* d,
    u32 a0, u32 a1, u32 a2, u32 a3, u32 b0, u32 b1)
{
    asm("mma.sync.aligned.m16n8k16.row.col.f32.f16.f16.f32 "
        "{%0,%1,%2,%3},{%4,%5,%6,%7},{%8,%9},{%0,%1,%2,%3};"
        : "+f"(d[0]), "+f"(d[1]), "+f"(d[2]), "+f"(d[3])
        : "r"(a0), "r"(a1), "r"(a2), "r"(a3), "r"(b0), "r"(b1));
}

// ---------------------------------------------------------------------------
// Kernel A: q = LayerNorm(hs @ Wk + bk) * ln_w + ln_b  -> fp16
// ---------------------------------------------------------------------------
__global__ __launch_bounds__(256) void qproj_ln_kernel(
    const float* __restrict__ hs, const float* __restrict__ Wk,
    const float* __restrict__ bk, const float* __restrict__ lnw,
    const float* __restrict__ lnb)
{
    __shared__ float As[64][16];
    __shared__ float Bs[16][256];
    const int tid = threadIdx.x;
    const int ty = tid >> 5;
    const int tx = tid & 31;
    const int m0 = blockIdx.x * 64;

    float c[8][8];
#pragma unroll
    for (int i = 0; i < 8; i++)
#pragma unroll
        for (int j = 0; j < 8; j++) c[i][j] = 0.f;

    for (int k0 = 0; k0 < DH; k0 += 16) {
        {
            int r = tid >> 2, k4 = tid & 3;
            float4 v = *(const float4*)(hs + (size_t)(m0 + r) * DH + k0 + k4 * 4);
            *(float4*)(&As[r][k4 * 4]) = v;
        }
#pragma unroll
        for (int u = 0; u < 4; u++) {
            int idx4 = tid + u * 256;
            int kk = idx4 >> 6, c4 = idx4 & 63;
            float4 v = *(const float4*)(Wk + (size_t)(k0 + kk) * DK + c4 * 4);
            *(float4*)(&Bs[kk][c4 * 4]) = v;
        }
        __syncthreads();
#pragma unroll
        for (int kk = 0; kk < 16; kk++) {
            float a[8], b[8];
#pragma unroll
            for (int i = 0; i < 8; i++) a[i] = As[ty * 8 + i][kk];
            float4 b0 = *(float4*)(&Bs[kk][tx * 8]);
            float4 b1 = *(float4*)(&Bs[kk][tx * 8 + 4]);
            b[0] = b0.x; b[1] = b0.y; b[2] = b0.z; b[3] = b0.w;
            b[4] = b1.x; b[5] = b1.y; b[6] = b1.z; b[7] = b1.w;
#pragma unroll
            for (int i = 0; i < 8; i++)
#pragma unroll
                for (int j = 0; j < 8; j++) c[i][j] += a[i] * b[j];
        }
        __syncthreads();
    }

    float bkv[8], lw[8], lb[8];
#pragma unroll
    for (int j = 0; j < 8; j++) {
        int col = tx * 8 + j;
        bkv[j] = bk[col]; lw[j] = lnw[col]; lb[j] = lnb[col];
    }
#pragma unroll
    for (int i = 0; i < 8; i++)
#pragma unroll
        for (int j = 0; j < 8; j++) c[i][j] += bkv[j];

#pragma unroll
    for (int i = 0; i < 8; i++) {
        float s = 0.f;
#pragma unroll
        for (int j = 0; j < 8; j++) s += c[i][j];
#pragma unroll
        for (int o = 16; o > 0; o >>= 1) s += __shfl_xor_sync(0xffffffffu, s, o);
        float mu = s * (1.0f / 256.0f);
        float v = 0.f;
#pragma unroll
        for (int j = 0; j < 8; j++) { float d = c[i][j] - mu; v += d * d; }
#pragma unroll
        for (int o = 16; o > 0; o >>= 1) v += __shfl_xor_sync(0xffffffffu, v, o);
        float rs = rsqrtf(v * (1.0f / 256.0f) + 1e-5f);
        float out[8];
#pragma unroll
        for (int j = 0; j < 8; j++) out[j] = (c[i][j] - mu) * rs * lw[j] + lb[j];
        __half* dst = g_qh + (size_t)(m0 + ty * 8 + i) * DK + tx * 8;
        *(uint4*)dst = make_uint4(packh2(out[0], out[1]), packh2(out[2], out[3]),
                                  packh2(out[4], out[5]), packh2(out[6], out[7]));
    }
}

// ---------------------------------------------------------------------------
// Kernel K: convert keys fp32 -> fp16 (natural layout)
// ---------------------------------------------------------------------------
__global__ __launch_bounds__(256) void kh_kernel(const float* __restrict__ mk)
{
    size_t i = ((size_t)blockIdx.x * 256 + threadIdx.x) * 8;
    float4 v0 = *(const float4*)(mk + i);
    float4 v1 = *(const float4*)(mk + i + 4);
    *(uint4*)(g_kh + i) = make_uint4(packh2(v0.x, v0.y), packh2(v0.z, v0.w),
                                     packh2(v1.x, v1.y), packh2(v1.z, v1.w));
}

// ---------------------------------------------------------------------------
// Kernel V: transpose values per block: g_vth[b][d][key] = fp16(mv[b][key][d])
// ---------------------------------------------------------------------------
__global__ __launch_bounds__(256) void vth_kernel(const float* __restrict__ mv)
{
    __shared__ float t[32][33];
    const int b = blockIdx.z, kt = blockIdx.y, dt = blockIdx.x;
    const int r = threadIdx.x >> 3, c4 = (threadIdx.x & 7) * 4;
    float4 v = *(const float4*)(mv + ((size_t)b * CAP + kt * 32 + r) * DK + dt * 32 + c4);
    t[r][c4] = v.x; t[r][c4 + 1] = v.y; t[r][c4 + 2] = v.z; t[r][c4 + 3] = v.w;
    __syncthreads();
    // write 4 consecutive keys at d = dt*32 + r
    uint2 o = make_uint2(packh2(t[c4][r], t[c4 + 1][r]),
                         packh2(t[c4 + 2][r], t[c4 + 3][r]));
    *(uint2*)(g_vth + ((size_t)b * DK + dt * 32 + r) * CAP + kt * 32 + c4) = o;
}

// ---------------------------------------------------------------------------
// Kernel B: per-block masked softmax attention, fp16 mma (m16n8k16).
// CTA = 64 queries x 16 memory blocks (grid 128 x 2), chunk = 32 keys.
// 8 warps. QK: warp w -> m-tile (w>>1), n16 = tiles (w&1)*2+{0,1}.
//          PV: warp w -> m32 group (w&1), n64 group (w>>2... w>>1).
// Strides (halves): Q/K 264 (words: 4r'+k' banks), Vt/P 40 (20r'+k') —
// all b32 fragment accesses bank-conflict-free.
// exp without max-subtraction is exact vs reference; p in [~0.8,1.25].
// ---------------------------------------------------------------------------
#define QSTR 264
#define KSTR 264
#define VSTR 40
#define PSTR 40
#define ATTN_SMEM (512 + 64*QSTR*2 + 32*KSTR*2 + 256*VSTR*2 + 64*PSTR*2)

extern __shared__ char sm_raw[];

__global__ __launch_bounds__(256, 1) void attn_kernel(const int* __restrict__ usage)
{
    float*  Ls  = (float*)sm_raw;                         // [64][2]
    __half* Qs  = (__half*)(sm_raw + 512);                // [64][264]
    __half* Ks  = Qs + 64 * QSTR;                         // [32][264]
    __half* Vts = Ks + 32 * KSTR;                         // [256][40]
    __half* Ps  = Vts + 256 * VSTR;                       // [64][40]

    const int tid  = threadIdx.x;
    const int w    = tid >> 5;
    const int lane = tid & 31;
    const int t4   = lane >> 2;     // row group 0..7
    const int tq   = lane & 3;      // quad col 0..3
    const int q0   = blockIdx.x * 64;
    const int b0   = blockIdx.y * (NBLK / 2);

    const int mw  = w >> 1;         // QK m-tile (16 rows)
    const int nt0 = (w & 1) * 2;    // QK first n8-tile
    const int mw2 = w & 1;          // PV m32 group
    const int nh2 = w >> 1;         // PV n64 group (0..3)

    // Q tile -> smem (once)
#pragma unroll
    for (int u = 0; u < 8; u++) {
        int idx4 = tid + u * 256;
        int row = idx4 >> 5, seg = idx4 & 31;
        uint4 v = *(const uint4*)(g_qh + ((size_t)(q0 + row) << 8) + seg * 8);
        *(uint4*)(Qs + row * QSTR + seg * 8) = v;
    }

    float O[2][8][4];
#pragma unroll
    for (int mt = 0; mt < 2; mt++)
#pragma unroll
        for (int nt = 0; nt < 8; nt++)
#pragma unroll
            for (int j = 0; j < 4; j++) O[mt][nt][j] = 0.f;

    const __half* qa = Qs + (mw * 16 + t4) * QSTR + tq * 2;
    const __half* kb = Ks + (nt0 * 8 + t4) * KSTR + tq * 2;
    const __half* pa = Ps + (mw2 * 32 + t4) * PSTR + tq * 2;
    const __half* vb = Vts + (nh2 * 64 + t4) * VSTR + tq * 2;

    for (int bb = 0; bb < NBLK / 2; bb++) {
        const int b = b0 + bb;
        const int use = __ldg(usage + b);
        const int nch = (use + 31) >> 5;

        float acc[2][8][4];
#pragma unroll
        for (int mt = 0; mt < 2; mt++)
#pragma unroll
            for (int nt = 0; nt < 8; nt++)
#pragma unroll
                for (int j = 0; j < 4; j++) acc[mt][nt][j] = 0.f;

        for (int ch = 0; ch < nch; ch++) {
            const int c0 = ch * 32;
            __syncthreads();   // prev chunk fully consumed (incl. Ls finalize reads)

            // fill K chunk + Vt chunk (fp16, vectorized)
            const __half* kg = g_kh + ((size_t)b * CAP + c0) * DK;
            const __half* vg = g_vth + (size_t)b * DK * CAP + c0;
#pragma unroll
            for (int u = 0; u < 4; u++) {
                int idx4 = tid + u * 256;
                int key = idx4 >> 5, seg = idx4 & 31;
                *(uint4*)(Ks + key * KSTR + seg * 8) =
                    *(const uint4*)(kg + (size_t)key * DK + seg * 8);
                int d = idx4 >> 2, k8 = idx4 & 3;
                *(uint4*)(Vts + d * VSTR + k8 * 8) =
                    *(const uint4*)(vg + (size_t)d * CAP + k8 * 8);
            }
            if (ch == 0 && tid < 128) Ls[tid] = 0.f;
            __syncthreads();

            // ---- S = Q K^T : warp computes m16 x n16 over k=256 ----
            float s0[4] = {0.f, 0.f, 0.f, 0.f};
            float s1[4] = {0.f, 0.f, 0.f, 0.f};
#pragma unroll
            for (int kk = 0; kk < 16; kk++) {
                u32 a0 = *(const u32*)(qa + kk * 16);
                u32 a1 = *(const u32*)(qa + kk * 16 + 8 * QSTR);
                u32 a2 = *(const u32*)(qa + kk * 16 + 8);
                u32 a3 = *(const u32*)(qa + kk * 16 + 8 * QSTR + 8);
                u32 b0 = *(const u32*)(kb + kk * 16);
                u32 b1 = *(const u32*)(kb + kk * 16 + 8);
                u32 b2 = *(const u32*)(kb + 8 * KSTR + kk * 16);
                u32 b3 = *(const u32*)(kb + 8 * KSTR + kk * 16 + 8);
                mma_f16(s0, a0, a1, a2, a3, b0, b1);
                mma_f16(s1, a0, a1, a2, a3, b2, b3);
            }

            // ---- mask + exp + store P + row-sum partials ----
            const int rem = use - c0;   // >= 1
            int cA = nt0 * 8 + 2 * tq;
            int cB = (nt0 + 1) * 8 + 2 * tq;
            float p00 = (cA     < rem) ? __expf(s0[0] * 0.0625f) : 0.f;
            float p01 = (cA + 1 < rem) ? __expf(s0[1] * 0.0625f) : 0.f;
            float p02 = (cA     < rem) ? __expf(s0[2] * 0.0625f) : 0.f;
            float p03 = (cA + 1 < rem) ? __expf(s0[3] * 0.0625f) : 0.f;
            float p10 = (cB     < rem) ? __expf(s1[0] * 0.0625f) : 0.f;
            float p11 = (cB + 1 < rem) ? __expf(s1[1] * 0.0625f) : 0.f;
            float p12 = (cB     < rem) ? __expf(s1[2] * 0.0625f) : 0.f;
            float p13 = (cB + 1 < rem) ? __expf(s1[3] * 0.0625f) : 0.f;

            __half* pr = Ps + (mw * 16 + t4) * PSTR + cA;
            *(u32*)pr = packh2(p00, p01);
            *(u32*)(pr + 8) = packh2(p10, p11);
            *(u32*)(pr + 8 * PSTR) = packh2(p02, p03);
            *(u32*)(pr + 8 * PSTR + 8) = packh2(p12, p13);

            float rs_lo = p00 + p01 + p10 + p11;
            float rs_hi = p02 + p03 + p12 + p13;
            rs_lo += __shfl_xor_sync(0xffffffffu, rs_lo, 1);
            rs_lo += __shfl_xor_sync(0xffffffffu, rs_lo, 2);
            rs_hi += __shfl_xor_sync(0xffffffffu, rs_hi, 1);
            rs_hi += __shfl_xor_sync(0xffffffffu, rs_hi, 2);
            if (tq == 0) {   // unique writer per (row, n-half)
                Ls[(mw * 16 + t4) * 2 + (w & 1)]       += rs_lo;
                Ls[(mw * 16 + t4 + 8) * 2 + (w & 1)]   += rs_hi;
            }
            __syncthreads();   // P + Ls visible

            // ---- acc += P @ V : warp computes m32 x n64 over k=32 ----
#pragma unroll
            for (int kk = 0; kk < 2; kk++) {
                u32 A[2][4];
#pragma unroll
                for (int mt = 0; mt < 2; mt++) {
                    const __half* pm = pa + mt * 16 * PSTR + kk * 16;
                    A[mt][0] = *(const u32*)(pm);
                    A[mt][1] = *(const u32*)(pm + 8 * PSTR);
                    A[mt][2] = *(const u32*)(pm + 8);
                    A[mt][3] = *(const u32*)(pm + 8 * PSTR + 8);
                }
#pragma unroll
                for (int nt = 0; nt < 8; nt++) {
                    u32 b0 = *(const u32*)(vb + nt * 8 * VSTR + kk * 16);
                    u32 b1 = *(const u32*)(vb + nt * 8 * VSTR + kk * 16 + 8);
                    mma_f16(acc[0][nt], A[0][0], A[0][1], A[0][2], A[0][3], b0, b1);
                    mma_f16(acc[1][nt], A[1][0], A[1][1], A[1][2], A[1][3], b0, b1);
                }
            }
        }

        // ---- finalize block: O += acc / rowsum ----
#pragma unroll
        for (int mt = 0; mt < 2; mt++) {
            int rlo = mw2 * 32 + mt * 16 + t4;
            float il = 1.0f / (Ls[rlo * 2] + Ls[rlo * 2 + 1]);
            float ih = 1.0f / (Ls[(rlo + 8) * 2] + Ls[(rlo + 8) * 2 + 1]);
#pragma unroll
            for (int nt = 0; nt < 8; nt++) {
                O[mt][nt][0] += acc[mt][nt][0] * il;
                O[mt][nt][1] += acc[mt][nt][1] * il;
                O[mt][nt][2] += acc[mt][nt][2] * ih;
                O[mt][nt][3] += acc[mt][nt][3] * ih;
            }
        }
    }

    // write partial retrieved values
    float* dst = blockIdx.y ? g_r1 : g_r0;
#pragma unroll
    for (int mt = 0; mt < 2; mt++) {
        int rlo = q0 + mw2 * 32 + mt * 16 + t4;
#pragma unroll
        for (int nt = 0; nt < 8; nt++) {
            int col = nh2 * 64 + nt * 8 + 2 * tq;
            *(float2*)(dst + (size_t)rlo * DK + col) =
                make_float2(O[mt][nt][0], O[mt][nt][1]);
            *(float2*)(dst + (size_t)(rlo + 8) * DK + col) =
                make_float2(O[mt][nt][2], O[mt][nt][3]);
        }
    }
}

// ---------------------------------------------------------------------------
// Kernel C: out = (g_r0 + g_r1) @ Wo + bo      [8192,256]x[256,768]
// ---------------------------------------------------------------------------
__global__ __launch_bounds__(256) void out_gemm_kernel(
    const float* __restrict__ Wo, const float* __restrict__ bo,
    float* __restrict__ out)
{
    __shared__ float As[64][20];
    __shared__ float Bs[16][64];
    const int tid = threadIdx.x;
    const int ty = tid >> 4;
    const int tx = tid & 15;
    const int m0 = blockIdx.x * 64;
    const int n0 = blockIdx.y * 64;

    float c[4][4];
#pragma unroll
    for (int i = 0; i < 4; i++)
#pragma unroll
        for (int j = 0; j < 4; j++) c[i][j] = 0.f;

    for (int k0 = 0; k0 < DK; k0 += 16) {
        {
            int r = tid >> 2, k4 = tid & 3;
            size_t off = (size_t)(m0 + r) * DK + k0 + k4 * 4;
            float4 v0 = *(const float4*)(g_r0 + off);
            float4 v1 = *(const float4*)(g_r1 + off);
            *(float4*)(&As[r][k4 * 4]) = make_float4(v0.x + v1.x, v0.y + v1.y,
                                                     v0.z + v1.z, v0.w + v1.w);
        }
        {
            int kk = tid >> 4, c4 = tid & 15;
            float4 v = *(const float4*)(Wo + (size_t)(k0 + kk) * DH + n0 + c4 * 4);
            *(float4*)(&Bs[kk][c4 * 4]) = v;
        }
        __syncthreads();
#pragma unroll
        for (int kk = 0; kk < 16; kk++) {
            float a[4];
#pragma unroll
            for (int i = 0; i < 4; i++) a[i] = As[ty * 4 + i][kk];
            float4 bv = *(float4*)(&Bs[kk][tx * 4]);
            float b[4] = {bv.x, bv.y, bv.z, bv.w};
#pragma unroll
            for (int i = 0; i < 4; i++)
#pragma unroll
                for (int j = 0; j < 4; j++) c[i][j] += a[i] * b[j];
        }
        __syncthreads();
    }

    float4 bv = *(const float4*)(bo + n0 + tx * 4);
    float bb[4] = {bv.x, bv.y, bv.z, bv.w};
#pragma unroll
    for (int i = 0; i < 4; i++) {
        float4 r = make_float4(c[i][0] + bb[0], c[i][1] + bb[1],
                               c[i][2] + bb[2], c[i][3] + bb[3]);
        *(float4*)(out + (size_t)(m0 + ty * 4 + i) * DH + n0 + tx * 4) = r;
    }
}

// ---------------------------------------------------------------------------
extern "C" void kernel_launch(void* const* d_in, const int* in_sizes, int n_in,
                              void* d_out, int out_size)
{
    const float* hs  = (const float*)d_in[0];
    const float* Wk  = (const float*)d_in[1];
    const float* bk  = (const float*)d_in[2];
    const float* lnw = (const float*)d_in[3];
    const float* lnb = (const float*)d_in[4];
    const float* mk  = (const float*)d_in[5];
    const float* mv  = (const float*)d_in[6];
    const float* Wo  = (const float*)d_in[7];
    const float* bo  = (const float*)d_in[8];
    const int* usage = (const int*)d_in[9];
    float* out = (float*)d_out;

    cudaFuncSetAttribute(attn_kernel, cudaFuncAttributeMaxDynamicSharedMemorySize,
                         ATTN_SMEM);

    qproj_ln_kernel<<<NQ / 64, 256>>>(hs, Wk, bk, lnw, lnb);
    kh_kernel<<<(NBLK * CAP * DK) / (256 * 8), 256>>>(mk);
    vth_kernel<<<dim3(DK / 32, CAP / 32, NBLK), 256>>>(mv);
    attn_kernel<<<dim3(NQ / 64, 2), 256, ATTN_SMEM>>>(usage);
    dim3 gc(NQ / 64, DH / 64);
    out_gemm_kernel<<<gc, 256>>>(Wo, bo, out);
}

// round 7
// speedup vs baseline: 6.0072x; 1.1738x over previous
#include <cuda_runtime.h>
#include <cuda_fp16.h>
#include <math.h>
#include <cstdint>

#define NBLK 32
#define CAP 1024
#define DK 256
#define DH 768
#define NQ 8192

typedef uint32_t u32;

// scratch (device globals: no allocation allowed)
__device__ __half g_qh[NQ * DK];            // layernormed queries, fp16
__device__ __half g_kh[NBLK * CAP * DK];    // keys, fp16
__device__ __half g_vth[NBLK * DK * CAP];   // values transposed [b][d][key], fp16
__device__ float  g_r0[NQ * DK];            // retrieved partial (blocks 0-15)
__device__ float  g_r1[NQ * DK];            // retrieved partial (blocks 16-31)

__device__ __forceinline__ u32 packh2(float a, float b) {
    __half2 h = __floats2half2_rn(a, b);
    return *(u32*)&h;
}

// fp16 tensor-core mma, fp32 accumulate
__device__ __forceinline__ void mma_f16(float* d,
    u32 a0, u32 a1, u32 a2, u32 a3, u32 b0, u32 b1)
{
    asm("mma.sync.aligned.m16n8k16.row.col.f32.f16.f16.f32 "
        "{%0,%1,%2,%3},{%4,%5,%6,%7},{%8,%9},{%0,%1,%2,%3};"
        : "+f"(d[0]), "+f"(d[1]), "+f"(d[2]), "+f"(d[3])
        : "r"(a0), "r"(a1), "r"(a2), "r"(a3), "r"(b0), "r"(b1));
}

__device__ __forceinline__ u32 s2u(const void* p) {
    u32 a;
    asm("{ .reg .u64 t; cvta.to.shared.u64 t, %1; cvt.u32.u64 %0, t; }"
        : "=r"(a) : "l"(p));
    return a;
}
__device__ __forceinline__ void cpa16(u32 dst, const void* src) {
    asm volatile("cp.async.cg.shared.global [%0], [%1], 16;"
                 :: "r"(dst), "l"(src) : "memory");
}
#define CPA_COMMIT() asm volatile("cp.async.commit_group;" ::: "memory")
#define CPA_WAIT1()  asm volatile("cp.async.wait_group 1;" ::: "memory")

// ---------------------------------------------------------------------------
// Kernel A: q = LayerNorm(hs @ Wk + bk) * ln_w + ln_b  -> fp16
// ---------------------------------------------------------------------------
__global__ __launch_bounds__(256) void qproj_ln_kernel(
    const float* __restrict__ hs, const float* __restrict__ Wk,
    const float* __restrict__ bk, const float* __restrict__ lnw,
    const float* __restrict__ lnb)
{
    __shared__ float As[64][16];
    __shared__ float Bs[16][256];
    const int tid = threadIdx.x;
    const int ty = tid >> 5;
    const int tx = tid & 31;
    const int m0 = blockIdx.x * 64;

    float c[8][8];
#pragma unroll
    for (int i = 0; i < 8; i++)
#pragma unroll
        for (int j = 0; j < 8; j++) c[i][j] = 0.f;

    for (int k0 = 0; k0 < DH; k0 += 16) {
        {
            int r = tid >> 2, k4 = tid & 3;
            float4 v = *(const float4*)(hs + (size_t)(m0 + r) * DH + k0 + k4 * 4);
            *(float4*)(&As[r][k4 * 4]) = v;
        }
#pragma unroll
        for (int u = 0; u < 4; u++) {
            int idx4 = tid + u * 256;
            int kk = idx4 >> 6, c4 = idx4 & 63;
            float4 v = *(const float4*)(Wk + (size_t)(k0 + kk) * DK + c4 * 4);
            *(float4*)(&Bs[kk][c4 * 4]) = v;
        }
        __syncthreads();
#pragma unroll
        for (int kk = 0; kk < 16; kk++) {
            float a[8], b[8];
#pragma unroll
            for (int i = 0; i < 8; i++) a[i] = As[ty * 8 + i][kk];
            float4 b0 = *(float4*)(&Bs[kk][tx * 8]);
            float4 b1 = *(float4*)(&Bs[kk][tx * 8 + 4]);
            b[0] = b0.x; b[1] = b0.y; b[2] = b0.z; b[3] = b0.w;
            b[4] = b1.x; b[5] = b1.y; b[6] = b1.z; b[7] = b1.w;
#pragma unroll
            for (int i = 0; i < 8; i++)
#pragma unroll
                for (int j = 0; j < 8; j++) c[i][j] += a[i] * b[j];
        }
        __syncthreads();
    }

    float bkv[8], lw[8], lb[8];
#pragma unroll
    for (int j = 0; j < 8; j++) {
        int col = tx * 8 + j;
        bkv[j] = bk[col]; lw[j] = lnw[col]; lb[j] = lnb[col];
    }
#pragma unroll
    for (int i = 0; i < 8; i++)
#pragma unroll
        for (int j = 0; j < 8; j++) c[i][j] += bkv[j];

#pragma unroll
    for (int i = 0; i < 8; i++) {
        float s = 0.f;
#pragma unroll
        for (int j = 0; j < 8; j++) s += c[i][j];
#pragma unroll
        for (int o = 16; o > 0; o >>= 1) s += __shfl_xor_sync(0xffffffffu, s, o);
        float mu = s * (1.0f / 256.0f);
        float v = 0.f;
#pragma unroll
        for (int j = 0; j < 8; j++) { float d = c[i][j] - mu; v += d * d; }
#pragma unroll
        for (int o = 16; o > 0; o >>= 1) v += __shfl_xor_sync(0xffffffffu, v, o);
        float rs = rsqrtf(v * (1.0f / 256.0f) + 1e-5f);
        float out[8];
#pragma unroll
        for (int j = 0; j < 8; j++) out[j] = (c[i][j] - mu) * rs * lw[j] + lb[j];
        __half* dst = g_qh + (size_t)(m0 + ty * 8 + i) * DK + tx * 8;
        *(uint4*)dst = make_uint4(packh2(out[0], out[1]), packh2(out[2], out[3]),
                                  packh2(out[4], out[5]), packh2(out[6], out[7]));
    }
}

// ---------------------------------------------------------------------------
// Kernel K: convert keys fp32 -> fp16 (natural layout)
// ---------------------------------------------------------------------------
__global__ __launch_bounds__(256) void kh_kernel(const float* __restrict__ mk)
{
    size_t i = ((size_t)blockIdx.x * 256 + threadIdx.x) * 8;
    float4 v0 = *(const float4*)(mk + i);
    float4 v1 = *(const float4*)(mk + i + 4);
    *(uint4*)(g_kh + i) = make_uint4(packh2(v0.x, v0.y), packh2(v0.z, v0.w),
                                     packh2(v1.x, v1.y), packh2(v1.z, v1.w));
}

// ---------------------------------------------------------------------------
// Kernel V: transpose values per block: g_vth[b][d][key] = fp16(mv[b][key][d])
// ---------------------------------------------------------------------------
__global__ __launch_bounds__(256) void vth_kernel(const float* __restrict__ mv)
{
    __shared__ float t[32][33];
    const int b = blockIdx.z, kt = blockIdx.y, dt = blockIdx.x;
    const int r = threadIdx.x >> 3, c4 = (threadIdx.x & 7) * 4;
    float4 v = *(const float4*)(mv + ((size_t)b * CAP + kt * 32 + r) * DK + dt * 32 + c4);
    t[r][c4] = v.x; t[r][c4 + 1] = v.y; t[r][c4 + 2] = v.z; t[r][c4 + 3] = v.w;
    __syncthreads();
    uint2 o = make_uint2(packh2(t[c4][r], t[c4 + 1][r]),
                         packh2(t[c4 + 2][r], t[c4 + 3][r]));
    *(uint2*)(g_vth + ((size_t)b * DK + dt * 32 + r) * CAP + kt * 32 + c4) = o;
}

// ---------------------------------------------------------------------------
// Kernel B: per-block masked softmax attention, fp16 mma, cp.async pipelined.
// CTA = 64 queries x 16 memory blocks (grid 128 x 2), chunk = 32 keys.
// Triple-buffered K / Vt chunk tiles: prefetch chunk i+1 (cp.async) overlaps
// compute of chunk i; buffer reuse distance 3 is certified by the two
// per-chunk __syncthreads() already present (no extra sync needed).
// ---------------------------------------------------------------------------
#define QSTR 264
#define KSTR 264
#define VSTR 40
#define PSTR 40
#define KBUF (32 * KSTR)     /* halves per K buffer  */
#define VBUF (256 * VSTR)    /* halves per Vt buffer */
#define ATTN_SMEM (512 + 64*QSTR*2 + 3*(KBUF + VBUF)*2 + 64*PSTR*2)

extern __shared__ char sm_raw[];

__global__ __launch_bounds__(256, 1) void attn_kernel(const int* __restrict__ usage)
{
    float*  Ls  = (float*)sm_raw;                         // [64][2]
    __half* Qs  = (__half*)(sm_raw + 512);                // [64][264]
    __half* Ks  = Qs + 64 * QSTR;                         // 3 x [32][264]
    __half* Vts = Ks + 3 * KBUF;                          // 3 x [256][40]
    __half* Ps  = Vts + 3 * VBUF;                         // [64][40]

    const u32 ks_u = s2u(Ks);
    const u32 vt_u = s2u(Vts);

    const int tid  = threadIdx.x;
    const int w    = tid >> 5;
    const int lane = tid & 31;
    const int t4   = lane >> 2;
    const int tq   = lane & 3;
    const int q0   = blockIdx.x * 64;
    const int b0   = blockIdx.y * (NBLK / 2);

    const int mw  = w >> 1;         // QK m-tile (16 rows)
    const int nt0 = (w & 1) * 2;    // QK first n8-tile
    const int mw2 = w & 1;          // PV m32 group
    const int nh2 = w >> 1;         // PV n64 group (0..3)

    // Q tile -> smem (once)
#pragma unroll
    for (int u = 0; u < 8; u++) {
        int idx4 = tid + u * 256;
        int row = idx4 >> 5, seg = idx4 & 31;
        uint4 v = *(const uint4*)(g_qh + ((size_t)(q0 + row) << 8) + seg * 8);
        *(uint4*)(Qs + row * QSTR + seg * 8) = v;
    }

    float O[2][8][4];
#pragma unroll
    for (int mt = 0; mt < 2; mt++)
#pragma unroll
        for (int nt = 0; nt < 8; nt++)
#pragma unroll
            for (int j = 0; j < 4; j++) O[mt][nt][j] = 0.f;

    // per-thread cp.async lane mapping (same for all chunks)
    const int ck_key = tid >> 5, ck_seg = tid & 31;   // + u*8 keys
    const int cv_d   = tid >> 2, cv_k8 = tid & 3;     // + u*64 d

    // prefetch chunk 0 of block b0 into buffer 0
    {
        const __half* kg = g_kh + (size_t)b0 * CAP * DK;
        const __half* vg = g_vth + (size_t)b0 * DK * CAP;
#pragma unroll
        for (int u = 0; u < 4; u++) {
            int key = ck_key + u * 8;
            cpa16(ks_u + (key * KSTR + ck_seg * 8) * 2, kg + (size_t)key * DK + ck_seg * 8);
            int d = cv_d + u * 64;
            cpa16(vt_u + (d * VSTR + cv_k8 * 8) * 2, vg + (size_t)d * CAP + cv_k8 * 8);
        }
        CPA_COMMIT();
    }

    int it = 0;
    for (int bb = 0; bb < NBLK / 2; bb++) {
        const int b = b0 + bb;
        const int use = __ldg(usage + b);
        const int nch = (use + 31) >> 5;

        float acc[2][8][4];
#pragma unroll
        for (int mt = 0; mt < 2; mt++)
#pragma unroll
            for (int nt = 0; nt < 8; nt++)
#pragma unroll
                for (int j = 0; j < 4; j++) acc[mt][nt][j] = 0.f;

        for (int ch = 0; ch < nch; ch++, it++) {
            const int buf = it % 3;
            const int c0 = ch * 32;

            // ---- prefetch next chunk (possibly next block) into buf (it+1)%3
            {
                int nb = b, nc = c0 + 32;
                bool has = true;
                if (ch + 1 >= nch) {
                    if (bb + 1 < NBLK / 2) { nb = b + 1; nc = 0; }
                    else has = false;
                }
                if (has) {
                    const int pb = (it + 1) % 3;
                    const __half* kg = g_kh + ((size_t)nb * CAP + nc) * DK;
                    const __half* vg = g_vth + (size_t)nb * DK * CAP + nc;
                    const u32 kd = ks_u + pb * KBUF * 2;
                    const u32 vd = vt_u + pb * VBUF * 2;
#pragma unroll
                    for (int u = 0; u < 4; u++) {
                        int key = ck_key + u * 8;
                        cpa16(kd + (key * KSTR + ck_seg * 8) * 2,
                              kg + (size_t)key * DK + ck_seg * 8);
                        int d = cv_d + u * 64;
                        cpa16(vd + (d * VSTR + cv_k8 * 8) * 2,
                              vg + (size_t)d * CAP + cv_k8 * 8);
                    }
                }
                CPA_COMMIT();
                CPA_WAIT1();   // current chunk (group it) complete
            }
            __syncthreads();   // chunk data visible; P/Ls of prev iter consumed

            const __half* qa = Qs + (mw * 16 + t4) * QSTR + tq * 2;
            const __half* kb = Ks + buf * KBUF + (nt0 * 8 + t4) * KSTR + tq * 2;

            // ---- S = Q K^T : warp computes m16 x n16 over k=256 ----
            float s0[4] = {0.f, 0.f, 0.f, 0.f};
            float s1[4] = {0.f, 0.f, 0.f, 0.f};
#pragma unroll
            for (int kk = 0; kk < 16; kk++) {
                u32 a0 = *(const u32*)(qa + kk * 16);
                u32 a1 = *(const u32*)(qa + kk * 16 + 8 * QSTR);
                u32 a2 = *(const u32*)(qa + kk * 16 + 8);
                u32 a3 = *(const u32*)(qa + kk * 16 + 8 * QSTR + 8);
                u32 b0v = *(const u32*)(kb + kk * 16);
                u32 b1v = *(const u32*)(kb + kk * 16 + 8);
                u32 b2v = *(const u32*)(kb + 8 * KSTR + kk * 16);
                u32 b3v = *(const u32*)(kb + 8 * KSTR + kk * 16 + 8);
                mma_f16(s0, a0, a1, a2, a3, b0v, b1v);
                mma_f16(s1, a0, a1, a2, a3, b2v, b3v);
            }

            // ---- mask + exp + store P + row-sum partials ----
            const int rem = use - c0;   // >= 1
            int cA = nt0 * 8 + 2 * tq;
            int cB = (nt0 + 1) * 8 + 2 * tq;
            float p00 = (cA     < rem) ? __expf(s0[0] * 0.0625f) : 0.f;
            float p01 = (cA + 1 < rem) ? __expf(s0[1] * 0.0625f) : 0.f;
            float p02 = (cA     < rem) ? __expf(s0[2] * 0.0625f) : 0.f;
            float p03 = (cA + 1 < rem) ? __expf(s0[3] * 0.0625f) : 0.f;
            float p10 = (cB     < rem) ? __expf(s1[0] * 0.0625f) : 0.f;
            float p11 = (cB + 1 < rem) ? __expf(s1[1] * 0.0625f) : 0.f;
            float p12 = (cB     < rem) ? __expf(s1[2] * 0.0625f) : 0.f;
            float p13 = (cB + 1 < rem) ? __expf(s1[3] * 0.0625f) : 0.f;

            __half* pr = Ps + (mw * 16 + t4) * PSTR + cA;
            *(u32*)pr = packh2(p00, p01);
            *(u32*)(pr + 8) = packh2(p10, p11);
            *(u32*)(pr + 8 * PSTR) = packh2(p02, p03);
            *(u32*)(pr + 8 * PSTR + 8) = packh2(p12, p13);

            float rs_lo = p00 + p01 + p10 + p11;
            float rs_hi = p02 + p03 + p12 + p13;
            rs_lo += __shfl_xor_sync(0xffffffffu, rs_lo, 1);
            rs_lo += __shfl_xor_sync(0xffffffffu, rs_lo, 2);
            rs_hi += __shfl_xor_sync(0xffffffffu, rs_hi, 1);
            rs_hi += __shfl_xor_sync(0xffffffffu, rs_hi, 2);
            if (tq == 0) {   // unique writer per (row, n-half)
                if (ch == 0) {
                    Ls[(mw * 16 + t4) * 2 + (w & 1)]     = rs_lo;
                    Ls[(mw * 16 + t4 + 8) * 2 + (w & 1)] = rs_hi;
                } else {
                    Ls[(mw * 16 + t4) * 2 + (w & 1)]     += rs_lo;
                    Ls[(mw * 16 + t4 + 8) * 2 + (w & 1)] += rs_hi;
                }
            }
            __syncthreads();   // P + Ls visible

            // ---- acc += P @ V : warp computes m32 x n64 over k=32 ----
            const __half* pa = Ps + (mw2 * 32 + t4) * PSTR + tq * 2;
            const __half* vb = Vts + buf * VBUF + (nh2 * 64 + t4) * VSTR + tq * 2;
#pragma unroll
            for (int kk = 0; kk < 2; kk++) {
                u32 A[2][4];
#pragma unroll
                for (int mt = 0; mt < 2; mt++) {
                    const __half* pm = pa + mt * 16 * PSTR + kk * 16;
                    A[mt][0] = *(const u32*)(pm);
                    A[mt][1] = *(const u32*)(pm + 8 * PSTR);
                    A[mt][2] = *(const u32*)(pm + 8);
                    A[mt][3] = *(const u32*)(pm + 8 * PSTR + 8);
                }
#pragma unroll
                for (int nt = 0; nt < 8; nt++) {
                    u32 b0v = *(const u32*)(vb + nt * 8 * VSTR + kk * 16);
                    u32 b1v = *(const u32*)(vb + nt * 8 * VSTR + kk * 16 + 8);
                    mma_f16(acc[0][nt], A[0][0], A[0][1], A[0][2], A[0][3], b0v, b1v);
                    mma_f16(acc[1][nt], A[1][0], A[1][1], A[1][2], A[1][3], b0v, b1v);
                }
            }
        }

        // ---- finalize block: O += acc / rowsum ----
#pragma unroll
        for (int mt = 0; mt < 2; mt++) {
            int rlo = mw2 * 32 + mt * 16 + t4;
            float il = 1.0f / (Ls[rlo * 2] + Ls[rlo * 2 + 1]);
            float ih = 1.0f / (Ls[(rlo + 8) * 2] + Ls[(rlo + 8) * 2 + 1]);
#pragma unroll
            for (int nt = 0; nt < 8; nt++) {
                O[mt][nt][0] += acc[mt][nt][0] * il;
                O[mt][nt][1] += acc[mt][nt][1] * il;
                O[mt][nt][2] += acc[mt][nt][2] * ih;
                O[mt][nt][3] += acc[mt][nt][3] * ih;
            }
        }
    }

    // write partial retrieved values
    float* dst = blockIdx.y ? g_r1 : g_r0;
#pragma unroll
    for (int mt = 0; mt < 2; mt++) {
        int rlo = q0 + mw2 * 32 + mt * 16 + t4;
#pragma unroll
        for (int nt = 0; nt < 8; nt++) {
            int col = nh2 * 64 + nt * 8 + 2 * tq;
            *(float2*)(dst + (size_t)rlo * DK + col) =
                make_float2(O[mt][nt][0], O[mt][nt][1]);
            *(float2*)(dst + (size_t)(rlo + 8) * DK + col) =
                make_float2(O[mt][nt][2], O[mt][nt][3]);
        }
    }
}

// ---------------------------------------------------------------------------
// Kernel C: out = (g_r0 + g_r1) @ Wo + bo      [8192,256]x[256,768]
// ---------------------------------------------------------------------------
__global__ __launch_bounds__(256) void out_gemm_kernel(
    const float* __restrict__ Wo, const float* __restrict__ bo,
    float* __restrict__ out)
{
    __shared__ float As[64][20];
    __shared__ float Bs[16][64];
    const int tid = threadIdx.x;
    const int ty = tid >> 4;
    const int tx = tid & 15;
    const int m0 = blockIdx.x * 64;
    const int n0 = blockIdx.y * 64;

    float c[4][4];
#pragma unroll
    for (int i = 0; i < 4; i++)
#pragma unroll
        for (int j = 0; j < 4; j++) c[i][j] = 0.f;

    for (int k0 = 0; k0 < DK; k0 += 16) {
        {
            int r = tid >> 2, k4 = tid & 3;
            size_t off = (size_t)(m0 + r) * DK + k0 + k4 * 4;
            float4 v0 = *(const float4*)(g_r0 + off);
            float4 v1 = *(const float4*)(g_r1 + off);
            *(float4*)(&As[r][k4 * 4]) = make_float4(v0.x + v1.x, v0.y + v1.y,
                                                     v0.z + v1.z, v0.w + v1.w);
        }
        {
            int kk = tid >> 4, c4 = tid & 15;
            float4 v = *(const float4*)(Wo + (size_t)(k0 + kk) * DH + n0 + c4 * 4);
            *(float4*)(&Bs[kk][c4 * 4]) = v;
        }
        __syncthreads();
#pragma unroll
        for (int kk = 0; kk < 16; kk++) {
            float a[4];
#pragma unroll
            for (int i = 0; i < 4; i++) a[i] = As[ty * 4 + i][kk];
            float4 bv = *(float4*)(&Bs[kk][tx * 4]);
            float b[4] = {bv.x, bv.y, bv.z, bv.w};
#pragma unroll
            for (int i = 0; i < 4; i++)
#pragma unroll
                for (int j = 0; j < 4; j++) c[i][j] += a[i] * b[j];
        }
        __syncthreads();
    }

    float4 bv = *(const float4*)(bo + n0 + tx * 4);
    float bb[4] = {bv.x, bv.y, bv.z, bv.w};
#pragma unroll
    for (int i = 0; i < 4; i++) {
        float4 r = make_float4(c[i][0] + bb[0], c[i][1] + bb[1],
                               c[i][2] + bb[2], c[i][3] + bb[3]);
        *(float4*)(out + (size_t)(m0 + ty * 4 + i) * DH + n0 + tx * 4) = r;
    }
}

// ---------------------------------------------------------------------------
extern "C" void kernel_launch(void* const* d_in, const int* in_sizes, int n_in,
                              void* d_out, int out_size)
{
    const float* hs  = (const float*)d_in[0];
    const float* Wk  = (const float*)d_in[1];
    const float* bk  = (const float*)d_in[2];
    const float* lnw = (const float*)d_in[3];
    const float* lnb = (const float*)d_in[4];
    const float* mk  = (const float*)d_in[5];
    const float* mv  = (const float*)d_in[6];
    const float* Wo  = (const float*)d_in[7];
    const float* bo  = (const float*)d_in[8];
    const int* usage = (const int*)d_in[9];
    float* out = (float*)d_out;

    cudaFuncSetAttribute(attn_kernel, cudaFuncAttributeMaxDynamicSharedMemorySize,
                         ATTN_SMEM);

    qproj_ln_kernel<<<NQ / 64, 256>>>(hs, Wk, bk, lnw, lnb);
    kh_kernel<<<(NBLK * CAP * DK) / (256 * 8), 256>>>(mk);
    vth_kernel<<<dim3(DK / 32, CAP / 32, NBLK), 256>>>(mv);
    attn_kernel<<<dim3(NQ / 64, 2), 256, ATTN_SMEM>>>(usage);
    dim3 gc(NQ / 64, DH / 64);
    out_gemm_kernel<<<gc, 256>>>(Wo, bo, out);
}

// round 8
// speedup vs baseline: 6.7267x; 1.1198x over previous
#include <cuda_runtime.h>
#include <cuda_fp16.h>
#include <math.h>
#include <cstdint>

#define NBLK 32
#define CAP 1024
#define DK 256
#define DH 768
#define NQ 8192

typedef uint32_t u32;

// scratch (device globals: no allocation allowed)
__device__ __half g_qh[NQ * DK];            // layernormed queries, fp16
__device__ __half g_kh[NBLK * CAP * DK];    // keys, fp16
__device__ __half g_vth[NBLK * DK * CAP];   // values transposed [b][d][key], fp16
__device__ float  g_r0[NQ * DK];            // retrieved partial (blocks 0-15)
__device__ float  g_r1[NQ * DK];            // retrieved partial (blocks 16-31)

__device__ __forceinline__ u32 packh2(float a, float b) {
    __half2 h = __floats2half2_rn(a, b);
    return *(u32*)&h;
}

// fp16 tensor-core mma, fp32 accumulate
__device__ __forceinline__ void mma_f16(float* d,
    u32 a0, u32 a1, u32 a2, u32 a3, u32 b0, u32 b1)
{
    asm("mma.sync.aligned.m16n8k16.row.col.f32.f16.f16.f32 "
        "{%0,%1,%2,%3},{%4,%5,%6,%7},{%8,%9},{%0,%1,%2,%3};"
        : "+f"(d[0]), "+f"(d[1]), "+f"(d[2]), "+f"(d[3])
        : "r"(a0), "r"(a1), "r"(a2), "r"(a3), "r"(b0), "r"(b1));
}

__device__ __forceinline__ u32 s2u(const void* p) {
    u32 a;
    asm("{ .reg .u64 t; cvta.to.shared.u64 t, %1; cvt.u32.u64 %0, t; }"
        : "=r"(a) : "l"(p));
    return a;
}
__device__ __forceinline__ void cpa16(u32 dst, const void* src) {
    asm volatile("cp.async.cg.shared.global [%0], [%1], 16;"
                 :: "r"(dst), "l"(src) : "memory");
}
#define CPA_COMMIT() asm volatile("cp.async.commit_group;" ::: "memory")
#define CPA_WAIT1()  asm volatile("cp.async.wait_group 1;" ::: "memory")

// ldmatrix x4: 4 8x8 b16 tiles; per-lane addr = one 16B row
#define LDSM4(r, a) asm volatile( \
    "ldmatrix.sync.aligned.m8n8.x4.shared.b16 {%0,%1,%2,%3}, [%4];" \
    : "=r"((r)[0]), "=r"((r)[1]), "=r"((r)[2]), "=r"((r)[3]) : "r"(a))

// ---------------------------------------------------------------------------
// Kernel A: q = LayerNorm(hs @ Wk + bk) * ln_w + ln_b  -> fp16
// ---------------------------------------------------------------------------
__global__ __launch_bounds__(256) void qproj_ln_kernel(
    const float* __restrict__ hs, const float* __restrict__ Wk,
    const float* __restrict__ bk, const float* __restrict__ lnw,
    const float* __restrict__ lnb)
{
    __shared__ float As[64][16];
    __shared__ float Bs[16][256];
    const int tid = threadIdx.x;
    const int ty = tid >> 5;
    const int tx = tid & 31;
    const int m0 = blockIdx.x * 64;

    float c[8][8];
#pragma unroll
    for (int i = 0; i < 8; i++)
#pragma unroll
        for (int j = 0; j < 8; j++) c[i][j] = 0.f;

    for (int k0 = 0; k0 < DH; k0 += 16) {
        {
            int r = tid >> 2, k4 = tid & 3;
            float4 v = *(const float4*)(hs + (size_t)(m0 + r) * DH + k0 + k4 * 4);
            *(float4*)(&As[r][k4 * 4]) = v;
        }
#pragma unroll
        for (int u = 0; u < 4; u++) {
            int idx4 = tid + u * 256;
            int kk = idx4 >> 6, c4 = idx4 & 63;
            float4 v = *(const float4*)(Wk + (size_t)(k0 + kk) * DK + c4 * 4);
            *(float4*)(&Bs[kk][c4 * 4]) = v;
        }
        __syncthreads();
#pragma unroll
        for (int kk = 0; kk < 16; kk++) {
            float a[8], b[8];
#pragma unroll
            for (int i = 0; i < 8; i++) a[i] = As[ty * 8 + i][kk];
            float4 b0 = *(float4*)(&Bs[kk][tx * 8]);
            float4 b1 = *(float4*)(&Bs[kk][tx * 8 + 4]);
            b[0] = b0.x; b[1] = b0.y; b[2] = b0.z; b[3] = b0.w;
            b[4] = b1.x; b[5] = b1.y; b[6] = b1.z; b[7] = b1.w;
#pragma unroll
            for (int i = 0; i < 8; i++)
#pragma unroll
                for (int j = 0; j < 8; j++) c[i][j] += a[i] * b[j];
        }
        __syncthreads();
    }

    float bkv[8], lw[8], lb[8];
#pragma unroll
    for (int j = 0; j < 8; j++) {
        int col = tx * 8 + j;
        bkv[j] = bk[col]; lw[j] = lnw[col]; lb[j] = lnb[col];
    }
#pragma unroll
    for (int i = 0; i < 8; i++)
#pragma unroll
        for (int j = 0; j < 8; j++) c[i][j] += bkv[j];

#pragma unroll
    for (int i = 0; i < 8; i++) {
        float s = 0.f;
#pragma unroll
        for (int j = 0; j < 8; j++) s += c[i][j];
#pragma unroll
        for (int o = 16; o > 0; o >>= 1) s += __shfl_xor_sync(0xffffffffu, s, o);
        float mu = s * (1.0f / 256.0f);
        float v = 0.f;
#pragma unroll
        for (int j = 0; j < 8; j++) { float d = c[i][j] - mu; v += d * d; }
#pragma unroll
        for (int o = 16; o > 0; o >>= 1) v += __shfl_xor_sync(0xffffffffu, v, o);
        float rs = rsqrtf(v * (1.0f / 256.0f) + 1e-5f);
        float out[8];
#pragma unroll
        for (int j = 0; j < 8; j++) out[j] = (c[i][j] - mu) * rs * lw[j] + lb[j];
        __half* dst = g_qh + (size_t)(m0 + ty * 8 + i) * DK + tx * 8;
        *(uint4*)dst = make_uint4(packh2(out[0], out[1]), packh2(out[2], out[3]),
                                  packh2(out[4], out[5]), packh2(out[6], out[7]));
    }
}

// ---------------------------------------------------------------------------
// Kernel K: convert keys fp32 -> fp16
// ---------------------------------------------------------------------------
__global__ __launch_bounds__(256) void kh_kernel(const float* __restrict__ mk)
{
    size_t i = ((size_t)blockIdx.x * 256 + threadIdx.x) * 8;
    float4 v0 = *(const float4*)(mk + i);
    float4 v1 = *(const float4*)(mk + i + 4);
    *(uint4*)(g_kh + i) = make_uint4(packh2(v0.x, v0.y), packh2(v0.z, v0.w),
                                     packh2(v1.x, v1.y), packh2(v1.z, v1.w));
}

// ---------------------------------------------------------------------------
// Kernel V: transpose values per block: g_vth[b][d][key] = fp16(mv[b][key][d])
// ---------------------------------------------------------------------------
__global__ __launch_bounds__(256) void vth_kernel(const float* __restrict__ mv)
{
    __shared__ float t[32][33];
    const int b = blockIdx.z, kt = blockIdx.y, dt = blockIdx.x;
    const int r = threadIdx.x >> 3, c4 = (threadIdx.x & 7) * 4;
    float4 v = *(const float4*)(mv + ((size_t)b * CAP + kt * 32 + r) * DK + dt * 32 + c4);
    t[r][c4] = v.x; t[r][c4 + 1] = v.y; t[r][c4 + 2] = v.z; t[r][c4 + 3] = v.w;
    __syncthreads();
    uint2 o = make_uint2(packh2(t[c4][r], t[c4 + 1][r]),
                         packh2(t[c4 + 2][r], t[c4 + 3][r]));
    *(uint2*)(g_vth + ((size_t)b * DK + dt * 32 + r) * CAP + kt * 32 + c4) = o;
}

// ---------------------------------------------------------------------------
// Kernel B: per-block masked softmax attention. fp16 mma + ldmatrix,
// chunk = 64 keys, double-buffered cp.async.
// CTA = 64 queries x 16 blocks (grid 128 x 2), 8 warps.
// QK: warp w -> m16 tile (w>>1), key-half n32 (w&1); 4 mma chains.
// PV: warp w -> m32 group (w&1), col group n64 (w>>1); k=64.
// Strides: Q/K 264 halves, Vt/P 72 halves -> LDSM phases & stores conflict-free.
// ---------------------------------------------------------------------------
#define QSTR 264
#define KSTR 264
#define VSTR 72
#define PSTR 72
#define KBUF (64 * KSTR)     /* halves per K buffer  */
#define VBUF (256 * VSTR)    /* halves per Vt buffer */
#define ATTN_SMEM (512 + 64*QSTR*2 + 2*KBUF*2 + 2*VBUF*2 + 64*PSTR*2)

extern __shared__ char sm_raw[];

__global__ __launch_bounds__(256, 1) void attn_kernel(const int* __restrict__ usage)
{
    float*  Ls  = (float*)sm_raw;                 // [64][2]
    __half* Qs  = (__half*)(sm_raw + 512);        // [64][264]
    __half* Ks  = Qs + 64 * QSTR;                 // 2 x [64][264]
    __half* Vts = Ks + 2 * KBUF;                  // 2 x [256][72]
    __half* Ps  = Vts + 2 * VBUF;                 // [64][72]

    const u32 qs_u = s2u(Qs);
    const u32 ks_u = s2u(Ks);
    const u32 vt_u = s2u(Vts);
    const u32 ps_u = s2u(Ps);

    const int tid  = threadIdx.x;
    const int w    = tid >> 5;
    const int lane = tid & 31;
    const int t4   = lane >> 2;
    const int tq   = lane & 3;
    const int q0   = blockIdx.x * 64;
    const int b0   = blockIdx.y * (NBLK / 2);

    const int mw = w >> 1;          // QK m16 tile
    const int nh = w & 1;           // QK key-half (n32)
    const int mg = w & 1;           // PV m32 group
    const int ng = w >> 1;          // PV n64 group

    // ldmatrix per-lane addresses (bytes): row = (lane&15), 16B-half = lane>>4
    const int l15 = lane & 15, lh = lane >> 4;
    const u32 qa  = qs_u + (u32)(((mw * 16 + l15) * QSTR + lh * 8) * 2);
    const u32 kb0 = (u32)(((nh * 32 + l15) * KSTR + lh * 8) * 2);        // + ks_u + buf
    const u32 kb1 = kb0 + 16 * KSTR * 2;
    const u32 pa0 = ps_u + (u32)(((mg * 32 + l15) * PSTR + lh * 8) * 2);
    const u32 pa1 = pa0 + 16 * PSTR * 2;
    const u32 vb0 = (u32)(((ng * 64 + l15) * VSTR + lh * 8) * 2);        // + vt_u + buf

    // Q tile -> smem (once)
#pragma unroll
    for (int u = 0; u < 8; u++) {
        int idx = tid + u * 256;
        int row = idx >> 5, seg = idx & 31;
        uint4 v = *(const uint4*)(g_qh + ((size_t)(q0 + row) << 8) + seg * 8);
        *(uint4*)(Qs + row * QSTR + seg * 8) = v;
    }

    float O[2][8][4];
#pragma unroll
    for (int mt = 0; mt < 2; mt++)
#pragma unroll
        for (int nt = 0; nt < 8; nt++)
#pragma unroll
            for (int j = 0; j < 4; j++) O[mt][nt][j] = 0.f;

    // prefetch chunk 0 of block b0 into buffer 0
    {
        const __half* kg = g_kh + (size_t)b0 * CAP * DK;
        const __half* vg = g_vth + (size_t)b0 * DK * CAP;
#pragma unroll
        for (int u = 0; u < 8; u++) {
            int idx = tid + u * 256;
            int key = idx >> 5, seg = idx & 31;
            cpa16(ks_u + (key * KSTR + seg * 8) * 2, kg + (size_t)key * DK + seg * 8);
            int d = idx >> 3, sg = idx & 7;
            cpa16(vt_u + (d * VSTR + sg * 8) * 2, vg + (size_t)d * CAP + sg * 8);
        }
        CPA_COMMIT();
    }

    int it = 0;
    for (int bb = 0; bb < NBLK / 2; bb++) {
        const int b = b0 + bb;
        const int use = __ldg(usage + b);
        const int nch = (use + 63) >> 6;

        float acc[2][8][4];
#pragma unroll
        for (int mt = 0; mt < 2; mt++)
#pragma unroll
            for (int nt = 0; nt < 8; nt++)
#pragma unroll
                for (int j = 0; j < 4; j++) acc[mt][nt][j] = 0.f;

        for (int ch = 0; ch < nch; ch++, it++) {
            const int buf = it & 1;
            const int c0 = ch * 64;

            __syncthreads();   // A: prev PV done -> buf^1 free; P consumed

            // prefetch next chunk (possibly next block) into buf^1
            {
                int nb = b, nc = c0 + 64;
                bool has = true;
                if (ch + 1 >= nch) {
                    if (bb + 1 < NBLK / 2) { nb = b + 1; nc = 0; }
                    else has = false;
                }
                if (has) {
                    const int pb = buf ^ 1;
                    const __half* kg = g_kh + ((size_t)nb * CAP + nc) * DK;
                    const __half* vg = g_vth + (size_t)nb * DK * CAP + nc;
                    const u32 kd = ks_u + pb * KBUF * 2;
                    const u32 vd = vt_u + pb * VBUF * 2;
#pragma unroll
                    for (int u = 0; u < 8; u++) {
                        int idx = tid + u * 256;
                        int key = idx >> 5, seg = idx & 31;
                        cpa16(kd + (key * KSTR + seg * 8) * 2,
                              kg + (size_t)key * DK + seg * 8);
                        int d = idx >> 3, sg = idx & 7;
                        cpa16(vd + (d * VSTR + sg * 8) * 2,
                              vg + (size_t)d * CAP + sg * 8);
                    }
                }
                CPA_COMMIT();
                CPA_WAIT1();   // current chunk's group complete
            }
            __syncthreads();   // B: chunk data visible to all warps

            // ---- S = Q K^T : m16 x n32 over k=256, 4 chains ----
            const u32 kbase = ks_u + buf * KBUF * 2;
            float s[4][4];
#pragma unroll
            for (int nt = 0; nt < 4; nt++)
#pragma unroll
                for (int j = 0; j < 4; j++) s[nt][j] = 0.f;
#pragma unroll
            for (int kk = 0; kk < 16; kk++) {
                u32 A[4], B0[4], B1[4];
                LDSM4(A, qa + kk * 32);
                LDSM4(B0, kbase + kb0 + kk * 32);
                LDSM4(B1, kbase + kb1 + kk * 32);
                mma_f16(s[0], A[0], A[1], A[2], A[3], B0[0], B0[2]);
                mma_f16(s[1], A[0], A[1], A[2], A[3], B0[1], B0[3]);
                mma_f16(s[2], A[0], A[1], A[2], A[3], B1[0], B1[2]);
                mma_f16(s[3], A[0], A[1], A[2], A[3], B1[1], B1[3]);
            }

            // ---- mask + exp + store P + row-sum partials ----
            const int rem = use - c0;   // >= 1
            const int row = mw * 16 + t4;
            float rs_lo = 0.f, rs_hi = 0.f;
#pragma unroll
            for (int nt = 0; nt < 4; nt++) {
                int col = nh * 32 + nt * 8 + 2 * tq;
                float p0 = (col     < rem) ? __expf(s[nt][0] * 0.0625f) : 0.f;
                float p1 = (col + 1 < rem) ? __expf(s[nt][1] * 0.0625f) : 0.f;
                float p2 = (col     < rem) ? __expf(s[nt][2] * 0.0625f) : 0.f;
                float p3 = (col + 1 < rem) ? __expf(s[nt][3] * 0.0625f) : 0.f;
                rs_lo += p0 + p1;
                rs_hi += p2 + p3;
                *(u32*)(Ps + row * PSTR + col)       = packh2(p0, p1);
                *(u32*)(Ps + (row + 8) * PSTR + col) = packh2(p2, p3);
            }
            rs_lo += __shfl_xor_sync(0xffffffffu, rs_lo, 1);
            rs_lo += __shfl_xor_sync(0xffffffffu, rs_lo, 2);
            rs_hi += __shfl_xor_sync(0xffffffffu, rs_hi, 1);
            rs_hi += __shfl_xor_sync(0xffffffffu, rs_hi, 2);
            if (tq == 0) {   // unique writer per (row, key-half)
                if (ch == 0) {
                    Ls[row * 2 + nh]       = rs_lo;
                    Ls[(row + 8) * 2 + nh] = rs_hi;
                } else {
                    Ls[row * 2 + nh]       += rs_lo;
                    Ls[(row + 8) * 2 + nh] += rs_hi;
                }
            }
            __syncthreads();   // C: P + Ls visible

            // ---- acc += P @ V : m32 x n64 over k=64 ----
            const u32 vbase = vt_u + buf * VBUF * 2;
#pragma unroll
            for (int kk = 0; kk < 4; kk++) {
                u32 A0[4], A1[4];
                LDSM4(A0, pa0 + kk * 32);
                LDSM4(A1, pa1 + kk * 32);
#pragma unroll
                for (int nt = 0; nt < 4; nt++) {
                    u32 B[4];
                    LDSM4(B, vbase + vb0 + nt * 16 * VSTR * 2 + kk * 32);
                    mma_f16(acc[0][2 * nt],     A0[0], A0[1], A0[2], A0[3], B[0], B[2]);
                    mma_f16(acc[0][2 * nt + 1], A0[0], A0[1], A0[2], A0[3], B[1], B[3]);
                    mma_f16(acc[1][2 * nt],     A1[0], A1[1], A1[2], A1[3], B[0], B[2]);
                    mma_f16(acc[1][2 * nt + 1], A1[0], A1[1], A1[2], A1[3], B[1], B[3]);
                }
            }
        }

        // ---- finalize block: O += acc / rowsum ----
#pragma unroll
        for (int mt = 0; mt < 2; mt++) {
            int r = mg * 32 + mt * 16 + t4;
            float il = 1.0f / (Ls[r * 2] + Ls[r * 2 + 1]);
            float ih = 1.0f / (Ls[(r + 8) * 2] + Ls[(r + 8) * 2 + 1]);
#pragma unroll
            for (int nt = 0; nt < 8; nt++) {
                O[mt][nt][0] += acc[mt][nt][0] * il;
                O[mt][nt][1] += acc[mt][nt][1] * il;
                O[mt][nt][2] += acc[mt][nt][2] * ih;
                O[mt][nt][3] += acc[mt][nt][3] * ih;
            }
        }
    }

    // write partial retrieved values
    float* dst = blockIdx.y ? g_r1 : g_r0;
#pragma unroll
    for (int mt = 0; mt < 2; mt++) {
        int r = q0 + mg * 32 + mt * 16 + t4;
#pragma unroll
        for (int nt = 0; nt < 8; nt++) {
            int col = ng * 64 + nt * 8 + 2 * tq;
            *(float2*)(dst + (size_t)r * DK + col) =
                make_float2(O[mt][nt][0], O[mt][nt][1]);
            *(float2*)(dst + (size_t)(r + 8) * DK + col) =
                make_float2(O[mt][nt][2], O[mt][nt][3]);
        }
    }
}

// ---------------------------------------------------------------------------
// Kernel C: out = (g_r0 + g_r1) @ Wo + bo      [8192,256]x[256,768]
// ---------------------------------------------------------------------------
__global__ __launch_bounds__(256) void out_gemm_kernel(
    const float* __restrict__ Wo, const float* __restrict__ bo,
    float* __restrict__ out)
{
    __shared__ float As[64][20];
    __shared__ float Bs[16][64];
    const int tid = threadIdx.x;
    const int ty = tid >> 4;
    const int tx = tid & 15;
    const int m0 = blockIdx.x * 64;
    const int n0 = blockIdx.y * 64;

    float c[4][4];
#pragma unroll
    for (int i = 0; i < 4; i++)
#pragma unroll
        for (int j = 0; j < 4; j++) c[i][j] = 0.f;

    for (int k0 = 0; k0 < DK; k0 += 16) {
        {
            int r = tid >> 2, k4 = tid & 3;
            size_t off = (size_t)(m0 + r) * DK + k0 + k4 * 4;
            float4 v0 = *(const float4*)(g_r0 + off);
            float4 v1 = *(const float4*)(g_r1 + off);
            *(float4*)(&As[r][k4 * 4]) = make_float4(v0.x + v1.x, v0.y + v1.y,
                                                     v0.z + v1.z, v0.w + v1.w);
        }
        {
            int kk = tid >> 4, c4 = tid & 15;
            float4 v = *(const float4*)(Wo + (size_t)(k0 + kk) * DH + n0 + c4 * 4);
            *(float4*)(&Bs[kk][c4 * 4]) = v;
        }
        __syncthreads();
#pragma unroll
        for (int kk = 0; kk < 16; kk++) {
            float a[4];
#pragma unroll
            for (int i = 0; i < 4; i++) a[i] = As[ty * 4 + i][kk];
            float4 bv = *(float4*)(&Bs[kk][tx * 4]);
            float b[4] = {bv.x, bv.y, bv.z, bv.w};
#pragma unroll
            for (int i = 0; i < 4; i++)
#pragma unroll
                for (int j = 0; j < 4; j++) c[i][j] += a[i] * b[j];
        }
        __syncthreads();
    }

    float4 bv = *(const float4*)(bo + n0 + tx * 4);
    float bb[4] = {bv.x, bv.y, bv.z, bv.w};
#pragma unroll
    for (int i = 0; i < 4; i++) {
        float4 r = make_float4(c[i][0] + bb[0], c[i][1] + bb[1],
                               c[i][2] + bb[2], c[i][3] + bb[3]);
        *(float4*)(out + (size_t)(m0 + ty * 4 + i) * DH + n0 + tx * 4) = r;
    }
}

// ---------------------------------------------------------------------------
extern "C" void kernel_launch(void* const* d_in, const int* in_sizes, int n_in,
                              void* d_out, int out_size)
{
    const float* hs  = (const float*)d_in[0];
    const float* Wk  = (const float*)d_in[1];
    const float* bk  = (const float*)d_in[2];
    const float* lnw = (const float*)d_in[3];
    const float* lnb = (const float*)d_in[4];
    const float* mk  = (const float*)d_in[5];
    const float* mv  = (const float*)d_in[6];
    const float* Wo  = (const float*)d_in[7];
    const float* bo  = (const float*)d_in[8];
    const int* usage = (const int*)d_in[9];
    float* out = (float*)d_out;

    cudaFuncSetAttribute(attn_kernel, cudaFuncAttributeMaxDynamicSharedMemorySize,
                         ATTN_SMEM);

    qproj_ln_kernel<<<NQ / 64, 256>>>(hs, Wk, bk, lnw, lnb);
    kh_kernel<<<(NBLK * CAP * DK) / (256 * 8), 256>>>(mk);
    vth_kernel<<<dim3(DK / 32, CAP / 32, NBLK), 256>>>(mv);
    attn_kernel<<<dim3(NQ / 64, 2), 256, ATTN_SMEM>>>(usage);
    dim3 gc(NQ / 64, DH / 64);
    out_gemm_kernel<<<gc, 256>>>(Wo, bo, out);
}